// round 3
// baseline (speedup 1.0000x reference)
#include <cuda_runtime.h>
#include <cstddef>

// Problem shape (fixed by the reference)
#define NTOK 8192
#define CDIM 1024
#define HDIM 128

// -------- scratch (allocation-free: static __device__ globals) --------
__device__ float g_q  [(size_t)NTOK * HDIM];          //   4 MB
__device__ float g_k  [(size_t)NTOK * HDIM];          //   4 MB
__device__ float g_vT [(size_t)CDIM * NTOK];          //  32 MB  (v transposed: [C, N])
__device__ float g_sc [(size_t)NTOK * NTOK];          // 256 MB  (scores -> softmax in place)
__device__ float g_att[(size_t)NTOK * CDIM];          //  32 MB

// ============================================================================
// Generic C = alpha * (A @ B^T) (+ bias[col]) tiled fp32 GEMM.
//   A: M x K  row-major
//   B: N x K  row-major   (so B^T is K x N)
//   C: M x N  row-major, or if TRANS_OUT: C[col*M + row] (i.e. C^T stored)
// Requires: M % 128 == 0, N % 128 == 0, K % 16 == 0 (true for all calls here).
// 256 threads, BM=BN=128, BK=16, 8x8 accumulator per thread.
// ============================================================================
template<bool TRANS_OUT, bool HAS_BIAS>
__global__ __launch_bounds__(256)
void gemm_abt(const float* __restrict__ A, const float* __restrict__ B,
              const float* __restrict__ bias, float* __restrict__ C,
              int M, int Ncols, int K, float alpha)
{
    constexpr int BM = 128, BN = 128, BK = 16, TM = 8, TN = 8;
    __shared__ float As[BK][BM + 4];
    __shared__ float Bs[BK][BN + 4];

    const int tid  = threadIdx.x;
    const int row0 = blockIdx.y * BM;
    const int col0 = blockIdx.x * BN;

    // loader mapping: 256 threads, 4 float4 columns per 16-wide k-slab
    const int lrow = tid >> 2;          // 0..63
    const int lcol = (tid & 3) << 2;    // 0,4,8,12

    // compute mapping: 16x16 threads, each 8x8 outputs
    const int trow = (tid >> 4) << 3;   // 0..120
    const int tcol = (tid & 15) << 3;   // 0..120

    float acc[TM][TN] = {};

    const float* Ab = A + (size_t)row0 * K;
    const float* Bb = B + (size_t)col0 * K;

    for (int k0 = 0; k0 < K; k0 += BK) {
        #pragma unroll
        for (int h = 0; h < 2; h++) {
            const int r = lrow + h * 64;
            float4 a = *(const float4*)(Ab + (size_t)r * K + (k0 + lcol));
            As[lcol + 0][r] = a.x; As[lcol + 1][r] = a.y;
            As[lcol + 2][r] = a.z; As[lcol + 3][r] = a.w;
            float4 b = *(const float4*)(Bb + (size_t)r * K + (k0 + lcol));
            Bs[lcol + 0][r] = b.x; Bs[lcol + 1][r] = b.y;
            Bs[lcol + 2][r] = b.z; Bs[lcol + 3][r] = b.w;
        }
        __syncthreads();

        #pragma unroll
        for (int kk = 0; kk < BK; kk++) {
            float4 a0 = *(const float4*)&As[kk][trow];
            float4 a1 = *(const float4*)&As[kk][trow + 4];
            float4 b0 = *(const float4*)&Bs[kk][tcol];
            float4 b1 = *(const float4*)&Bs[kk][tcol + 4];
            float ra[TM] = {a0.x, a0.y, a0.z, a0.w, a1.x, a1.y, a1.z, a1.w};
            float rb[TN] = {b0.x, b0.y, b0.z, b0.w, b1.x, b1.y, b1.z, b1.w};
            #pragma unroll
            for (int i = 0; i < TM; i++)
                #pragma unroll
                for (int j = 0; j < TN; j++)
                    acc[i][j] += ra[i] * rb[j];
        }
        __syncthreads();
    }

    #pragma unroll
    for (int i = 0; i < TM; i++) {
        const int r = row0 + trow + i;
        #pragma unroll
        for (int j = 0; j < TN; j++) {
            const int c = col0 + tcol + j;
            float v = acc[i][j] * alpha;
            if (HAS_BIAS) v += __ldg(&bias[c]);
            if (TRANS_OUT) C[(size_t)c * M + r] = v;
            else           C[(size_t)r * Ncols + c] = v;
        }
    }
}

// ============================================================================
// Row softmax over n=8192 columns, scale folded in. One block per row,
// 256 threads x 32 elements held in registers; two block reductions.
// ============================================================================
__global__ __launch_bounds__(256)
void softmax_rows(float* __restrict__ S, int n, float scale)
{
    __shared__ float red[256];
    const int tid = threadIdx.x;
    float* row = S + (size_t)blockIdx.x * n;

    constexpr int PER = NTOK / 256;   // 32
    float v[PER];
    float mx = -1e30f;
    #pragma unroll
    for (int i = 0; i < PER; i++) {
        v[i] = row[i * 256 + tid] * scale;
        mx = fmaxf(mx, v[i]);
    }
    red[tid] = mx;
    __syncthreads();
    #pragma unroll
    for (int s = 128; s > 0; s >>= 1) {
        if (tid < s) red[tid] = fmaxf(red[tid], red[tid + s]);
        __syncthreads();
    }
    mx = red[0];
    __syncthreads();

    float sum = 0.f;
    #pragma unroll
    for (int i = 0; i < PER; i++) {
        v[i] = __expf(v[i] - mx);
        sum += v[i];
    }
    red[tid] = sum;
    __syncthreads();
    #pragma unroll
    for (int s = 128; s > 0; s >>= 1) {
        if (tid < s) red[tid] += red[tid + s];
        __syncthreads();
    }
    const float inv = 1.0f / red[0];
    #pragma unroll
    for (int i = 0; i < PER; i++)
        row[i * 256 + tid] = v[i] * inv;
}

// ============================================================================
extern "C" void kernel_launch(void* const* d_in, const int* /*in_sizes*/, int /*n_in*/,
                              void* d_out, int /*out_size*/)
{
    const float* x  = (const float*)d_in[0];
    const float* Wq = (const float*)d_in[1];
    const float* bq = (const float*)d_in[2];
    const float* Wk = (const float*)d_in[3];
    const float* bk = (const float*)d_in[4];
    const float* Wv = (const float*)d_in[5];
    const float* bv = (const float*)d_in[6];
    const float* Wo = (const float*)d_in[7];
    const float* bo = (const float*)d_in[8];
    float* out = (float*)d_out;

    float *q, *k, *vT, *sc, *att;
    cudaGetSymbolAddress((void**)&q,   g_q);
    cudaGetSymbolAddress((void**)&k,   g_k);
    cudaGetSymbolAddress((void**)&vT,  g_vT);
    cudaGetSymbolAddress((void**)&sc,  g_sc);
    cudaGetSymbolAddress((void**)&att, g_att);

    const float scale = 0.08838834764831845f;  // 1/sqrt(128)
    const dim3 blk(256);

    // q = x @ Wq^T + bq   (8192 x 128)
    gemm_abt<false, true><<<dim3(HDIM / 128, NTOK / 128), blk>>>(
        x, Wq, bq, q, NTOK, HDIM, CDIM, 1.0f);
    // k = x @ Wk^T + bk   (8192 x 128)
    gemm_abt<false, true><<<dim3(HDIM / 128, NTOK / 128), blk>>>(
        x, Wk, bk, k, NTOK, HDIM, CDIM, 1.0f);
    // vT = (x @ Wv^T + bv)^T   stored as (1024 x 8192)
    gemm_abt<true, true><<<dim3(CDIM / 128, NTOK / 128), blk>>>(
        x, Wv, bv, vT, NTOK, CDIM, CDIM, 1.0f);
    // scores = q @ k^T   (8192 x 8192)
    gemm_abt<false, false><<<dim3(NTOK / 128, NTOK / 128), blk>>>(
        q, k, nullptr, sc, NTOK, NTOK, HDIM, 1.0f);
    // softmax(scores * scale) rows, in place
    softmax_rows<<<NTOK, 256>>>(sc, NTOK, scale);
    // att = attn @ v = attn @ (vT)^T   (8192 x 1024)  -- dominant GEMM, K=8192
    gemm_abt<false, false><<<dim3(CDIM / 128, NTOK / 128), blk>>>(
        sc, vT, nullptr, att, NTOK, CDIM, NTOK, 1.0f);
    // out = att @ Wo^T + bo   (8192 x 1024)
    gemm_abt<false, true><<<dim3(CDIM / 128, NTOK / 128), blk>>>(
        att, Wo, bo, out, NTOK, CDIM, CDIM, 1.0f);
}

// round 7
// speedup vs baseline: 3.1486x; 3.1486x over previous
#include <cuda_runtime.h>
#include <cuda_bf16.h>
#include <cstdint>
#include <cstddef>

#define NTOK 8192
#define CDIM 1024
#define HDIM 128

// ======================= scratch (static, allocation-free) ==================
__device__ __align__(16) __nv_bfloat16 g_xh [(size_t)NTOK * CDIM];
__device__ __align__(16) __nv_bfloat16 g_xl [(size_t)NTOK * CDIM];
__device__ __align__(16) __nv_bfloat16 g_wqh[HDIM * CDIM];
__device__ __align__(16) __nv_bfloat16 g_wql[HDIM * CDIM];
__device__ __align__(16) __nv_bfloat16 g_wkh[HDIM * CDIM];
__device__ __align__(16) __nv_bfloat16 g_wkl[HDIM * CDIM];
__device__ __align__(16) __nv_bfloat16 g_wvh[CDIM * CDIM];
__device__ __align__(16) __nv_bfloat16 g_wvl[CDIM * CDIM];
__device__ __align__(16) __nv_bfloat16 g_woh[CDIM * CDIM];
__device__ __align__(16) __nv_bfloat16 g_wol[CDIM * CDIM];
__device__ __align__(16) __nv_bfloat16 g_qh [(size_t)NTOK * HDIM];
__device__ __align__(16) __nv_bfloat16 g_ql [(size_t)NTOK * HDIM];
__device__ __align__(16) __nv_bfloat16 g_kh [(size_t)NTOK * HDIM];
__device__ __align__(16) __nv_bfloat16 g_kl [(size_t)NTOK * HDIM];
__device__ __align__(16) __nv_bfloat16 g_vth[(size_t)CDIM * NTOK];   // v^T pair [C][N]
__device__ __align__(16) __nv_bfloat16 g_vtl[(size_t)CDIM * NTOK];
__device__ float g_sc[(size_t)NTOK * NTOK];                          // scores fp32
__device__ __align__(16) __nv_bfloat16 g_ah [(size_t)NTOK * NTOK];   // attn pair
__device__ __align__(16) __nv_bfloat16 g_al [(size_t)NTOK * NTOK];
__device__ __align__(16) __nv_bfloat16 g_oh [(size_t)NTOK * CDIM];   // attn@v pair
__device__ __align__(16) __nv_bfloat16 g_ol [(size_t)NTOK * CDIM];

// ======================= PTX helpers (sm_80+ portable only) =================
__device__ __forceinline__ uint32_t smem_u32(const void* p) {
    uint32_t a;
    asm("{ .reg .u64 t; cvta.to.shared.u64 t, %1; cvt.u32.u64 %0, t; }" : "=r"(a) : "l"(p));
    return a;
}
#define CP16(sm, gp) \
    asm volatile("cp.async.cg.shared.global [%0], [%1], 16;" :: "r"(sm), "l"(gp))
#define CP_COMMIT() asm volatile("cp.async.commit_group;" ::: "memory")
#define CP_WAIT1()  asm volatile("cp.async.wait_group 1;" ::: "memory")

__device__ __forceinline__ void ldsm4(uint32_t& r0, uint32_t& r1, uint32_t& r2,
                                      uint32_t& r3, uint32_t a) {
    asm volatile("ldmatrix.sync.aligned.m8n8.x4.shared.b16 {%0,%1,%2,%3}, [%4];"
                 : "=r"(r0), "=r"(r1), "=r"(r2), "=r"(r3) : "r"(a));
}
__device__ __forceinline__ void mma16816(float* c, const uint32_t* a, const uint32_t* b) {
    asm volatile("mma.sync.aligned.m16n8k16.row.col.f32.bf16.bf16.f32 "
                 "{%0,%1,%2,%3}, {%4,%5,%6,%7}, {%8,%9}, {%0,%1,%2,%3};"
                 : "+f"(c[0]), "+f"(c[1]), "+f"(c[2]), "+f"(c[3])
                 : "r"(a[0]), "r"(a[1]), "r"(a[2]), "r"(a[3]), "r"(b[0]), "r"(b[1]));
}

// ======================= warp-mma split-bf16 GEMM ===========================
// C = A @ B^T (+bias[col]).  A: M x K pair (hi/lo bf16), B: N x K pair.
// MODE 0: fp32 C row-major   MODE 1: bf16 pair row-major
// MODE 2: bf16 pair TRANSPOSED C[col*ldc + row] (ldc = M)
// BM=BN=128, BK=64, 3-stage cp.async pipeline, 256 threads (8 warps, 64x32 tiles).
// Requires M%128==0, N%128==0, K%64==0.
static constexpr int STAGES = 3;
static constexpr int BK     = 64;
static constexpr int MATB   = 128 * 128;        // 16 KB per matrix per stage (128 rows x 128B)
static constexpr int STAGEB = 4 * MATB;         // 64 KB per stage
static constexpr int SMEM_BYTES = STAGES * STAGEB;  // 192 KB

#define SWZ(off) ((off) ^ (((off) >> 3) & 0x70))

template<int MODE>
__global__ __launch_bounds__(256, 1)
void gemm_mma(const __nv_bfloat16* __restrict__ Ah, const __nv_bfloat16* __restrict__ Al,
              const __nv_bfloat16* __restrict__ Bh, const __nv_bfloat16* __restrict__ Bl,
              const float* __restrict__ bias,
              float* __restrict__ Cf,
              __nv_bfloat16* __restrict__ Chi, __nv_bfloat16* __restrict__ Clo,
              int M, int N, int K, int ldc)
{
    extern __shared__ __align__(128) char smem[];
    const uint32_t sb = smem_u32(smem);

    const int tid  = threadIdx.x;
    const int lane = tid & 31;
    const int wid  = tid >> 5;
    const int warp_m = wid & 1;        // 2 warps over M
    const int warp_n = wid >> 1;       // 4 warps over N
    const int row0 = blockIdx.y * 128;
    const int col0 = blockIdx.x * 128;

    // ---- loader mapping: 4 mats x 64 threads; 16 chunks of 16B each -------
    const __nv_bfloat16* mats[4] = {
        Ah + (size_t)row0 * K, Al + (size_t)row0 * K,
        Bh + (size_t)col0 * K, Bl + (size_t)col0 * K };
    const int mat = tid >> 6;
    const int lt  = tid & 63;
    const __nv_bfloat16* mbase = mats[mat];
    const uint32_t sm_mat = sb + (uint32_t)mat * MATB;

    auto load_stage = [&](int s, int buf) {
        const __nv_bfloat16* gp = mbase + (size_t)s * BK;
        const uint32_t sbuf = sm_mat + (uint32_t)buf * STAGEB;
        #pragma unroll
        for (int i = 0; i < 16; i++) {
            int c = i * 64 + lt;           // chunk id 0..1023
            int r = c >> 3, g = c & 7;     // row, 16B-chunk within 128B row
            uint32_t off = (uint32_t)(r * 128 + g * 16);
            CP16(sbuf + SWZ(off), gp + (size_t)r * K + g * 8);
        }
    };

    float acc[4][4][4];
    #pragma unroll
    for (int i = 0; i < 4; i++)
        #pragma unroll
        for (int j = 0; j < 4; j++)
            #pragma unroll
            for (int e = 0; e < 4; e++) acc[i][j][e] = 0.f;

    const int S = K / BK;
    load_stage(0, 0); CP_COMMIT();
    if (S > 1) load_stage(1, 1);
    CP_COMMIT();

    const int sel = lane >> 3, r8 = lane & 7;   // ldmatrix lane mapping

    for (int s = 0; s < S; s++) {
        CP_WAIT1();
        __syncthreads();
        if (s + 2 < S) load_stage(s + 2, (s + 2) % STAGES);
        CP_COMMIT();

        const uint32_t stg = sb + (uint32_t)(s % STAGES) * STAGEB;
        const uint32_t Abh = stg, Abl = stg + MATB, Bbh = stg + 2 * MATB, Bbl = stg + 3 * MATB;

        #pragma unroll
        for (int kk = 0; kk < 4; kk++) {       // four k16 slabs per BK=64 stage
            uint32_t ah[4][4], al[4][4], bh[2][4], bl[2][4];
            // A tiles: lanes 0-7 rows 0-7 @k0; 8-15 rows 8-15 @k0; 16-23 rows 0-7 @k+8; 24-31 rows 8-15 @k+8
            #pragma unroll
            for (int mt = 0; mt < 4; mt++) {
                int row = warp_m * 64 + mt * 16 + (sel & 1) * 8 + r8;
                int cidx = kk * 2 + (sel >> 1);                 // 16B column 0..7
                uint32_t off = (uint32_t)(row * 128) + ((uint32_t)(cidx ^ (row & 7)) * 16);
                ldsm4(ah[mt][0], ah[mt][1], ah[mt][2], ah[mt][3], Abh + off);
                ldsm4(al[mt][0], al[mt][1], al[mt][2], al[mt][3], Abl + off);
            }
            // B tiles: lanes 0-7 n 0-7 @k0; 8-15 n 0-7 @k+8; 16-23 n 8-15 @k0; 24-31 n 8-15 @k+8
            #pragma unroll
            for (int nb = 0; nb < 2; nb++) {
                int n = warp_n * 32 + nb * 16 + (sel >> 1) * 8 + r8;
                int cidx = kk * 2 + (sel & 1);
                uint32_t off = (uint32_t)(n * 128) + ((uint32_t)(cidx ^ (n & 7)) * 16);
                ldsm4(bh[nb][0], bh[nb][1], bh[nb][2], bh[nb][3], Bbh + off);
                ldsm4(bl[nb][0], bl[nb][1], bl[nb][2], bl[nb][3], Bbl + off);
            }
            #pragma unroll
            for (int mt = 0; mt < 4; mt++)
                #pragma unroll
                for (int nt = 0; nt < 4; nt++) {
                    const uint32_t* bph = &bh[nt >> 1][(nt & 1) * 2];
                    const uint32_t* bpl = &bl[nt >> 1][(nt & 1) * 2];
                    mma16816(acc[mt][nt], ah[mt], bph);   // hi*hi
                    mma16816(acc[mt][nt], ah[mt], bpl);   // hi*lo
                    mma16816(acc[mt][nt], al[mt], bph);   // lo*hi
                }
        }
    }
    __syncthreads();

    // ---- epilogue: frags -> padded SMEM fp32 -> coalesced global ----------
    float* cs = (float*)smem;                   // 128 x 133 fp32 (68 KB < 192 KB)
    const int g = lane >> 2, tq = lane & 3;
    #pragma unroll
    for (int mt = 0; mt < 4; mt++) {
        int rb = warp_m * 64 + mt * 16 + g;
        #pragma unroll
        for (int nt = 0; nt < 4; nt++) {
            int cb = warp_n * 32 + nt * 8 + tq * 2;
            cs[rb * 133 + cb]           = acc[mt][nt][0];
            cs[rb * 133 + cb + 1]       = acc[mt][nt][1];
            cs[(rb + 8) * 133 + cb]     = acc[mt][nt][2];
            cs[(rb + 8) * 133 + cb + 1] = acc[mt][nt][3];
        }
    }
    __syncthreads();

    if (MODE == 0) {
        const int col = tid & 127, half = tid >> 7;
        const float bv = bias ? __ldg(bias + col0 + col) : 0.f;
        for (int r = half; r < 128; r += 2)
            Cf[(size_t)(row0 + r) * ldc + col0 + col] = cs[r * 133 + col] + bv;
    } else if (MODE == 1) {
        const int col = tid & 127, half = tid >> 7;
        const float bv = bias ? __ldg(bias + col0 + col) : 0.f;
        for (int r = half; r < 128; r += 2) {
            float v = cs[r * 133 + col] + bv;
            __nv_bfloat16 h = __float2bfloat16(v);
            __nv_bfloat16 l = __float2bfloat16(v - __bfloat162float(h));
            size_t idx = (size_t)(row0 + r) * ldc + col0 + col;
            Chi[idx] = h; Clo[idx] = l;
        }
    } else {
        const int row = tid & 127, half = tid >> 7;
        for (int c = half; c < 128; c += 2) {
            float v = cs[row * 133 + c] + (bias ? __ldg(bias + col0 + c) : 0.f);
            __nv_bfloat16 h = __float2bfloat16(v);
            __nv_bfloat16 l = __float2bfloat16(v - __bfloat162float(h));
            size_t idx = (size_t)(col0 + c) * ldc + row0 + row;
            Chi[idx] = h; Clo[idx] = l;
        }
    }
}

// ======================= fp32 -> bf16 pair conversion =======================
__global__ __launch_bounds__(256)
void convert_pair(const float* __restrict__ s, __nv_bfloat16* __restrict__ h,
                  __nv_bfloat16* __restrict__ l, size_t n)
{
    size_t i = (size_t)blockIdx.x * blockDim.x + threadIdx.x;
    const size_t stride = (size_t)gridDim.x * blockDim.x;
    for (; i < n; i += stride) {
        float v = s[i];
        __nv_bfloat16 hi = __float2bfloat16(v);
        h[i] = hi;
        l[i] = __float2bfloat16(v - __bfloat162float(hi));
    }
}

// ======================= softmax (fp32 in -> bf16 pair out) =================
__global__ __launch_bounds__(256)
void softmax_pair(const float* __restrict__ S, __nv_bfloat16* __restrict__ Ah,
                  __nv_bfloat16* __restrict__ Al, int n, float scale)
{
    __shared__ float red[256];
    const int tid = threadIdx.x;
    const float* row = S + (size_t)blockIdx.x * n;
    __nv_bfloat16* oh = Ah + (size_t)blockIdx.x * n;
    __nv_bfloat16* ol = Al + (size_t)blockIdx.x * n;

    constexpr int PER = NTOK / 256;  // 32
    float v[PER];
    float mx = -1e30f;
    #pragma unroll
    for (int i = 0; i < PER; i++) {
        v[i] = row[i * 256 + tid] * scale;
        mx = fmaxf(mx, v[i]);
    }
    red[tid] = mx; __syncthreads();
    #pragma unroll
    for (int s = 128; s > 0; s >>= 1) {
        if (tid < s) red[tid] = fmaxf(red[tid], red[tid + s]);
        __syncthreads();
    }
    mx = red[0]; __syncthreads();

    float sum = 0.f;
    #pragma unroll
    for (int i = 0; i < PER; i++) { v[i] = __expf(v[i] - mx); sum += v[i]; }
    red[tid] = sum; __syncthreads();
    #pragma unroll
    for (int s = 128; s > 0; s >>= 1) {
        if (tid < s) red[tid] += red[tid + s];
        __syncthreads();
    }
    const float inv = 1.0f / red[0];
    #pragma unroll
    for (int i = 0; i < PER; i++) {
        float a = v[i] * inv;
        __nv_bfloat16 h = __float2bfloat16(a);
        oh[i * 256 + tid] = h;
        ol[i * 256 + tid] = __float2bfloat16(a - __bfloat162float(h));
    }
}

// ======================= launch =============================================
extern "C" void kernel_launch(void* const* d_in, const int* /*in_sizes*/, int /*n_in*/,
                              void* d_out, int /*out_size*/)
{
    const float* x  = (const float*)d_in[0];
    const float* Wq = (const float*)d_in[1];
    const float* bq = (const float*)d_in[2];
    const float* Wk = (const float*)d_in[3];
    const float* bk = (const float*)d_in[4];
    const float* Wv = (const float*)d_in[5];
    const float* bv = (const float*)d_in[6];
    const float* Wo = (const float*)d_in[7];
    const float* bo = (const float*)d_in[8];
    float* out = (float*)d_out;

    __nv_bfloat16 *xh, *xl, *wqh, *wql, *wkh, *wkl, *wvh, *wvl, *woh, *wol;
    __nv_bfloat16 *qh, *ql, *kh, *kl, *vth, *vtl, *ah, *al, *oh, *ol;
    float* sc;
    cudaGetSymbolAddress((void**)&xh,  g_xh);  cudaGetSymbolAddress((void**)&xl,  g_xl);
    cudaGetSymbolAddress((void**)&wqh, g_wqh); cudaGetSymbolAddress((void**)&wql, g_wql);
    cudaGetSymbolAddress((void**)&wkh, g_wkh); cudaGetSymbolAddress((void**)&wkl, g_wkl);
    cudaGetSymbolAddress((void**)&wvh, g_wvh); cudaGetSymbolAddress((void**)&wvl, g_wvl);
    cudaGetSymbolAddress((void**)&woh, g_woh); cudaGetSymbolAddress((void**)&wol, g_wol);
    cudaGetSymbolAddress((void**)&qh,  g_qh);  cudaGetSymbolAddress((void**)&ql,  g_ql);
    cudaGetSymbolAddress((void**)&kh,  g_kh);  cudaGetSymbolAddress((void**)&kl,  g_kl);
    cudaGetSymbolAddress((void**)&vth, g_vth); cudaGetSymbolAddress((void**)&vtl, g_vtl);
    cudaGetSymbolAddress((void**)&ah,  g_ah);  cudaGetSymbolAddress((void**)&al,  g_al);
    cudaGetSymbolAddress((void**)&oh,  g_oh);  cudaGetSymbolAddress((void**)&ol,  g_ol);
    cudaGetSymbolAddress((void**)&sc,  g_sc);

    cudaFuncSetAttribute(gemm_mma<0>, cudaFuncAttributeMaxDynamicSharedMemorySize, SMEM_BYTES);
    cudaFuncSetAttribute(gemm_mma<1>, cudaFuncAttributeMaxDynamicSharedMemorySize, SMEM_BYTES);
    cudaFuncSetAttribute(gemm_mma<2>, cudaFuncAttributeMaxDynamicSharedMemorySize, SMEM_BYTES);

    const float scale = 0.08838834764831845f;  // 1/sqrt(128)
    const dim3 blk(256);

    // input conversions to bf16 hi/lo pairs
    convert_pair<<<1184, 256>>>(x,  xh,  xl,  (size_t)NTOK * CDIM);
    convert_pair<<<64,  256>>>(Wq, wqh, wql, (size_t)HDIM * CDIM);
    convert_pair<<<64,  256>>>(Wk, wkh, wkl, (size_t)HDIM * CDIM);
    convert_pair<<<512, 256>>>(Wv, wvh, wvl, (size_t)CDIM * CDIM);
    convert_pair<<<512, 256>>>(Wo, woh, wol, (size_t)CDIM * CDIM);

    // q = x @ Wq^T + bq -> pair (8192 x 128)
    gemm_mma<1><<<dim3(1, 64), blk, SMEM_BYTES>>>(xh, xl, wqh, wql, bq,
        nullptr, qh, ql, NTOK, HDIM, CDIM, HDIM);
    // k = x @ Wk^T + bk -> pair
    gemm_mma<1><<<dim3(1, 64), blk, SMEM_BYTES>>>(xh, xl, wkh, wkl, bk,
        nullptr, kh, kl, NTOK, HDIM, CDIM, HDIM);
    // v^T = (x @ Wv^T + bv)^T -> pair, stored [C, N]
    gemm_mma<2><<<dim3(8, 64), blk, SMEM_BYTES>>>(xh, xl, wvh, wvl, bv,
        nullptr, vth, vtl, NTOK, CDIM, CDIM, NTOK);
    // scores = q @ k^T -> fp32 (scale folded into softmax)
    gemm_mma<0><<<dim3(64, 64), blk, SMEM_BYTES>>>(qh, ql, kh, kl, nullptr,
        sc, nullptr, nullptr, NTOK, NTOK, HDIM, NTOK);
    // softmax rows -> attn pair
    softmax_pair<<<NTOK, 256>>>(sc, ah, al, NTOK, scale);
    // att = attn @ (v^T)^T -> pair (dominant GEMM, K=8192)
    gemm_mma<1><<<dim3(8, 64), blk, SMEM_BYTES>>>(ah, al, vth, vtl, nullptr,
        nullptr, oh, ol, NTOK, CDIM, NTOK, CDIM);
    // out = att @ Wo^T + bo -> fp32
    gemm_mma<0><<<dim3(8, 64), blk, SMEM_BYTES>>>(oh, ol, woh, wol, bo,
        out, nullptr, nullptr, NTOK, CDIM, CDIM, CDIM);
}

// round 12
// speedup vs baseline: 3.1740x; 1.0081x over previous
#include <cuda_runtime.h>
#include <cuda_bf16.h>
#include <cstdint>
#include <cstddef>

#define NTOK 8192
#define CDIM 1024
#define HDIM 128

// ======================= scratch (static, allocation-free) ==================
__device__ __align__(16) __nv_bfloat16 g_xh [(size_t)NTOK * CDIM];
__device__ __align__(16) __nv_bfloat16 g_xl [(size_t)NTOK * CDIM];
__device__ __align__(16) __nv_bfloat16 g_wqh[HDIM * CDIM];
__device__ __align__(16) __nv_bfloat16 g_wql[HDIM * CDIM];
__device__ __align__(16) __nv_bfloat16 g_wkh[HDIM * CDIM];
__device__ __align__(16) __nv_bfloat16 g_wkl[HDIM * CDIM];
__device__ __align__(16) __nv_bfloat16 g_wvh[CDIM * CDIM];
__device__ __align__(16) __nv_bfloat16 g_wvl[CDIM * CDIM];
__device__ __align__(16) __nv_bfloat16 g_woh[CDIM * CDIM];
__device__ __align__(16) __nv_bfloat16 g_wol[CDIM * CDIM];
__device__ __align__(16) __nv_bfloat16 g_qh [(size_t)NTOK * HDIM];
__device__ __align__(16) __nv_bfloat16 g_ql [(size_t)NTOK * HDIM];
__device__ __align__(16) __nv_bfloat16 g_kh [(size_t)NTOK * HDIM];
__device__ __align__(16) __nv_bfloat16 g_kl [(size_t)NTOK * HDIM];
__device__ __align__(16) __nv_bfloat16 g_vth[(size_t)CDIM * NTOK];   // v^T pair [C][N]
__device__ __align__(16) __nv_bfloat16 g_vtl[(size_t)CDIM * NTOK];
__device__ float g_sc[(size_t)NTOK * NTOK];                          // scores fp32
__device__ __align__(16) __nv_bfloat16 g_ah [(size_t)NTOK * NTOK];   // attn pair
__device__ __align__(16) __nv_bfloat16 g_al [(size_t)NTOK * NTOK];
__device__ __align__(16) __nv_bfloat16 g_oh [(size_t)NTOK * CDIM];   // attn@v pair
__device__ __align__(16) __nv_bfloat16 g_ol [(size_t)NTOK * CDIM];

// ======================= PTX helpers (sm_80+ portable only) =================
__device__ __forceinline__ uint32_t smem_u32(const void* p) {
    uint32_t a;
    asm("{ .reg .u64 t; cvta.to.shared.u64 t, %1; cvt.u32.u64 %0, t; }" : "=r"(a) : "l"(p));
    return a;
}
#define CP16(sm, gp) \
    asm volatile("cp.async.cg.shared.global [%0], [%1], 16;" :: "r"(sm), "l"(gp))
#define CP_COMMIT() asm volatile("cp.async.commit_group;" ::: "memory")
#define CP_WAIT1()  asm volatile("cp.async.wait_group 1;" ::: "memory")

__device__ __forceinline__ void ldsm4(uint32_t& r0, uint32_t& r1, uint32_t& r2,
                                      uint32_t& r3, uint32_t a) {
    asm volatile("ldmatrix.sync.aligned.m8n8.x4.shared.b16 {%0,%1,%2,%3}, [%4];"
                 : "=r"(r0), "=r"(r1), "=r"(r2), "=r"(r3) : "r"(a));
}
__device__ __forceinline__ void mma16816(float* c, const uint32_t* a, const uint32_t* b) {
    asm volatile("mma.sync.aligned.m16n8k16.row.col.f32.bf16.bf16.f32 "
                 "{%0,%1,%2,%3}, {%4,%5,%6,%7}, {%8,%9}, {%0,%1,%2,%3};"
                 : "+f"(c[0]), "+f"(c[1]), "+f"(c[2]), "+f"(c[3])
                 : "r"(a[0]), "r"(a[1]), "r"(a[2]), "r"(a[3]), "r"(b[0]), "r"(b[1]));
}

// FMA-pipe exp2: y in [-126, 0]; ~2.4e-6 max rel err. No MUFU.
__device__ __forceinline__ float fast_exp2(float y) {
    y = fmaxf(y, -120.f);
    const int   ni = __float2int_rn(y);
    const float f  = y - (float)ni;
    // 2^f = e^{f ln2}, degree-5 Taylor (|f| <= 0.5)
    float p = 1.3333558146e-3f;
    p = fmaf(p, f, 9.6181291076e-3f);
    p = fmaf(p, f, 5.5504108664e-2f);
    p = fmaf(p, f, 2.4022650696e-1f);
    p = fmaf(p, f, 6.9314718056e-1f);
    p = fmaf(p, f, 1.0f);
    return p * __int_as_float((ni + 127) << 23);
}

// ======================= warp-mma split-bf16 GEMM ===========================
// C = A @ B^T (+bias[col]).  A: M x K pair (hi/lo bf16), B: N x K pair.
// MODE 0: fp32 C row-major   MODE 1: bf16 pair row-major
// MODE 2: bf16 pair TRANSPOSED C[col*ldc + row] (ldc = M)
// BM=BN=128, BK=64, 3-stage cp.async pipeline, 256 threads (8 warps, 64x32 tiles).
static constexpr int STAGES = 3;
static constexpr int BK     = 64;
static constexpr int MATB   = 128 * 128;        // 16 KB per matrix per stage
static constexpr int STAGEB = 4 * MATB;         // 64 KB per stage
static constexpr int SMEM_BYTES = STAGES * STAGEB;  // 192 KB

#define SWZ(off) ((off) ^ (((off) >> 3) & 0x70))

template<int MODE>
__global__ __launch_bounds__(256, 1)
void gemm_mma(const __nv_bfloat16* __restrict__ Ah, const __nv_bfloat16* __restrict__ Al,
              const __nv_bfloat16* __restrict__ Bh, const __nv_bfloat16* __restrict__ Bl,
              const float* __restrict__ bias,
              float* __restrict__ Cf,
              __nv_bfloat16* __restrict__ Chi, __nv_bfloat16* __restrict__ Clo,
              int M, int N, int K, int ldc)
{
    extern __shared__ __align__(128) char smem[];
    const uint32_t sb = smem_u32(smem);

    const int tid  = threadIdx.x;
    const int lane = tid & 31;
    const int wid  = tid >> 5;
    const int warp_m = wid & 1;        // 2 warps over M
    const int warp_n = wid >> 1;       // 4 warps over N
    const int row0 = blockIdx.y * 128;
    const int col0 = blockIdx.x * 128;

    const __nv_bfloat16* mats[4] = {
        Ah + (size_t)row0 * K, Al + (size_t)row0 * K,
        Bh + (size_t)col0 * K, Bl + (size_t)col0 * K };
    const int mat = tid >> 6;
    const int lt  = tid & 63;
    const __nv_bfloat16* mbase = mats[mat];
    const uint32_t sm_mat = sb + (uint32_t)mat * MATB;

    auto load_stage = [&](int s, int buf) {
        const __nv_bfloat16* gp = mbase + (size_t)s * BK;
        const uint32_t sbuf = sm_mat + (uint32_t)buf * STAGEB;
        #pragma unroll
        for (int i = 0; i < 16; i++) {
            int c = i * 64 + lt;
            int r = c >> 3, g = c & 7;
            uint32_t off = (uint32_t)(r * 128 + g * 16);
            CP16(sbuf + SWZ(off), gp + (size_t)r * K + g * 8);
        }
    };

    float acc[4][4][4];
    #pragma unroll
    for (int i = 0; i < 4; i++)
        #pragma unroll
        for (int j = 0; j < 4; j++)
            #pragma unroll
            for (int e = 0; e < 4; e++) acc[i][j][e] = 0.f;

    const int S = K / BK;
    load_stage(0, 0); CP_COMMIT();
    if (S > 1) load_stage(1, 1);
    CP_COMMIT();

    const int sel = lane >> 3, r8 = lane & 7;

    for (int s = 0; s < S; s++) {
        CP_WAIT1();
        __syncthreads();
        if (s + 2 < S) load_stage(s + 2, (s + 2) % STAGES);
        CP_COMMIT();

        const uint32_t stg = sb + (uint32_t)(s % STAGES) * STAGEB;
        const uint32_t Abh = stg, Abl = stg + MATB, Bbh = stg + 2 * MATB, Bbl = stg + 3 * MATB;

        #pragma unroll
        for (int kk = 0; kk < 4; kk++) {
            uint32_t ah[4][4], al[4][4], bh[2][4], bl[2][4];
            #pragma unroll
            for (int mt = 0; mt < 4; mt++) {
                int row = warp_m * 64 + mt * 16 + (sel & 1) * 8 + r8;
                int cidx = kk * 2 + (sel >> 1);
                uint32_t off = (uint32_t)(row * 128) + ((uint32_t)(cidx ^ (row & 7)) * 16);
                ldsm4(ah[mt][0], ah[mt][1], ah[mt][2], ah[mt][3], Abh + off);
                ldsm4(al[mt][0], al[mt][1], al[mt][2], al[mt][3], Abl + off);
            }
            #pragma unroll
            for (int nb = 0; nb < 2; nb++) {
                int n = warp_n * 32 + nb * 16 + (sel >> 1) * 8 + r8;
                int cidx = kk * 2 + (sel & 1);
                uint32_t off = (uint32_t)(n * 128) + ((uint32_t)(cidx ^ (n & 7)) * 16);
                ldsm4(bh[nb][0], bh[nb][1], bh[nb][2], bh[nb][3], Bbh + off);
                ldsm4(bl[nb][0], bl[nb][1], bl[nb][2], bl[nb][3], Bbl + off);
            }
            #pragma unroll
            for (int mt = 0; mt < 4; mt++)
                #pragma unroll
                for (int nt = 0; nt < 4; nt++) {
                    const uint32_t* bph = &bh[nt >> 1][(nt & 1) * 2];
                    const uint32_t* bpl = &bl[nt >> 1][(nt & 1) * 2];
                    mma16816(acc[mt][nt], ah[mt], bph);   // hi*hi
                    mma16816(acc[mt][nt], ah[mt], bpl);   // hi*lo
                    mma16816(acc[mt][nt], al[mt], bph);   // lo*hi
                }
        }
    }
    __syncthreads();

    // ---- epilogue: frags -> padded SMEM fp32 -> coalesced global ----------
    float* cs = (float*)smem;                   // 128 x 133 fp32
    const int g = lane >> 2, tq = lane & 3;
    #pragma unroll
    for (int mt = 0; mt < 4; mt++) {
        int rb = warp_m * 64 + mt * 16 + g;
        #pragma unroll
        for (int nt = 0; nt < 4; nt++) {
            int cb = warp_n * 32 + nt * 8 + tq * 2;
            cs[rb * 133 + cb]           = acc[mt][nt][0];
            cs[rb * 133 + cb + 1]       = acc[mt][nt][1];
            cs[(rb + 8) * 133 + cb]     = acc[mt][nt][2];
            cs[(rb + 8) * 133 + cb + 1] = acc[mt][nt][3];
        }
    }
    __syncthreads();

    if (MODE == 0) {
        const int col = tid & 127, half = tid >> 7;
        const float bv = bias ? __ldg(bias + col0 + col) : 0.f;
        for (int r = half; r < 128; r += 2)
            Cf[(size_t)(row0 + r) * ldc + col0 + col] = cs[r * 133 + col] + bv;
    } else if (MODE == 1) {
        const int col = tid & 127, half = tid >> 7;
        const float bv = bias ? __ldg(bias + col0 + col) : 0.f;
        for (int r = half; r < 128; r += 2) {
            float v = cs[r * 133 + col] + bv;
            __nv_bfloat16 h = __float2bfloat16(v);
            __nv_bfloat16 l = __float2bfloat16(v - __bfloat162float(h));
            size_t idx = (size_t)(row0 + r) * ldc + col0 + col;
            Chi[idx] = h; Clo[idx] = l;
        }
    } else {
        const int row = tid & 127, half = tid >> 7;
        for (int c = half; c < 128; c += 2) {
            float v = cs[row * 133 + c] + (bias ? __ldg(bias + col0 + c) : 0.f);
            __nv_bfloat16 h = __float2bfloat16(v);
            __nv_bfloat16 l = __float2bfloat16(v - __bfloat162float(h));
            size_t idx = (size_t)(col0 + c) * ldc + row0 + row;
            Chi[idx] = h; Clo[idx] = l;
        }
    }
}

// ======================= fp32 -> bf16 pair conversion (float4) ==============
__global__ __launch_bounds__(256)
void convert_pair(const float* __restrict__ s, __nv_bfloat16* __restrict__ h,
                  __nv_bfloat16* __restrict__ l, size_t n4)   // n4 = n/4
{
    size_t i = (size_t)blockIdx.x * blockDim.x + threadIdx.x;
    const size_t stride = (size_t)gridDim.x * blockDim.x;
    for (; i < n4; i += stride) {
        float4 v = ((const float4*)s)[i];
        __nv_bfloat16 h0 = __float2bfloat16(v.x), h1 = __float2bfloat16(v.y);
        __nv_bfloat16 h2 = __float2bfloat16(v.z), h3 = __float2bfloat16(v.w);
        __nv_bfloat162 hp0 = {h0, h1}, hp1 = {h2, h3};
        __nv_bfloat162 lp0 = {__float2bfloat16(v.x - __bfloat162float(h0)),
                              __float2bfloat16(v.y - __bfloat162float(h1))};
        __nv_bfloat162 lp1 = {__float2bfloat16(v.z - __bfloat162float(h2)),
                              __float2bfloat16(v.w - __bfloat162float(h3))};
        ((__nv_bfloat162*)h)[i * 2]     = hp0;
        ((__nv_bfloat162*)h)[i * 2 + 1] = hp1;
        ((__nv_bfloat162*)l)[i * 2]     = lp0;
        ((__nv_bfloat162*)l)[i * 2 + 1] = lp1;
    }
}

// ======================= softmax (FMA-pipe exp2, no MUFU) ===================
__global__ __launch_bounds__(256)
void softmax_pair(const float* __restrict__ S, __nv_bfloat16* __restrict__ Ah,
                  __nv_bfloat16* __restrict__ Al, int n, float scale)
{
    __shared__ float red[256];
    const int tid = threadIdx.x;
    const float* row = S + (size_t)blockIdx.x * n;
    __nv_bfloat16* oh = Ah + (size_t)blockIdx.x * n;
    __nv_bfloat16* ol = Al + (size_t)blockIdx.x * n;

    constexpr int PER = NTOK / 256;  // 32
    float v[PER];
    float mx = -1e30f;
    #pragma unroll
    for (int i = 0; i < PER; i++) {
        v[i] = row[i * 256 + tid];
        mx = fmaxf(mx, v[i]);
    }
    red[tid] = mx; __syncthreads();
    #pragma unroll
    for (int s = 128; s > 0; s >>= 1) {
        if (tid < s) red[tid] = fmaxf(red[tid], red[tid + s]);
        __syncthreads();
    }
    mx = red[0]; __syncthreads();

    const float k2 = scale * 1.4426950408889634f;   // scale * log2(e)
    float sum = 0.f;
    #pragma unroll
    for (int i = 0; i < PER; i++) {
        v[i] = fast_exp2((v[i] - mx) * k2);
        sum += v[i];
    }
    red[tid] = sum; __syncthreads();
    #pragma unroll
    for (int s = 128; s > 0; s >>= 1) {
        if (tid < s) red[tid] += red[tid + s];
        __syncthreads();
    }
    const float inv = 1.0f / red[0];
    #pragma unroll
    for (int i = 0; i < PER; i++) {
        float a = v[i] * inv;
        __nv_bfloat16 h = __float2bfloat16(a);
        oh[i * 256 + tid] = h;
        ol[i * 256 + tid] = __float2bfloat16(a - __bfloat162float(h));
    }
}

// ======================= launch =============================================
extern "C" void kernel_launch(void* const* d_in, const int* /*in_sizes*/, int /*n_in*/,
                              void* d_out, int /*out_size*/)
{
    const float* x  = (const float*)d_in[0];
    const float* Wq = (const float*)d_in[1];
    const float* bq = (const float*)d_in[2];
    const float* Wk = (const float*)d_in[3];
    const float* bk = (const float*)d_in[4];
    const float* Wv = (const float*)d_in[5];
    const float* bv = (const float*)d_in[6];
    const float* Wo = (const float*)d_in[7];
    const float* bo = (const float*)d_in[8];
    float* out = (float*)d_out;

    __nv_bfloat16 *xh, *xl, *wqh, *wql, *wkh, *wkl, *wvh, *wvl, *woh, *wol;
    __nv_bfloat16 *qh, *ql, *kh, *kl, *vth, *vtl, *ah, *al, *oh, *ol;
    float* sc;
    cudaGetSymbolAddress((void**)&xh,  g_xh);  cudaGetSymbolAddress((void**)&xl,  g_xl);
    cudaGetSymbolAddress((void**)&wqh, g_wqh); cudaGetSymbolAddress((void**)&wql, g_wql);
    cudaGetSymbolAddress((void**)&wkh, g_wkh); cudaGetSymbolAddress((void**)&wkl, g_wkl);
    cudaGetSymbolAddress((void**)&wvh, g_wvh); cudaGetSymbolAddress((void**)&wvl, g_wvl);
    cudaGetSymbolAddress((void**)&woh, g_woh); cudaGetSymbolAddress((void**)&wol, g_wol);
    cudaGetSymbolAddress((void**)&qh,  g_qh);  cudaGetSymbolAddress((void**)&ql,  g_ql);
    cudaGetSymbolAddress((void**)&kh,  g_kh);  cudaGetSymbolAddress((void**)&kl,  g_kl);
    cudaGetSymbolAddress((void**)&vth, g_vth); cudaGetSymbolAddress((void**)&vtl, g_vtl);
    cudaGetSymbolAddress((void**)&ah,  g_ah);  cudaGetSymbolAddress((void**)&al,  g_al);
    cudaGetSymbolAddress((void**)&oh,  g_oh);  cudaGetSymbolAddress((void**)&ol,  g_ol);
    cudaGetSymbolAddress((void**)&sc,  g_sc);

    cudaFuncSetAttribute(gemm_mma<0>, cudaFuncAttributeMaxDynamicSharedMemorySize, SMEM_BYTES);
    cudaFuncSetAttribute(gemm_mma<1>, cudaFuncAttributeMaxDynamicSharedMemorySize, SMEM_BYTES);
    cudaFuncSetAttribute(gemm_mma<2>, cudaFuncAttributeMaxDynamicSharedMemorySize, SMEM_BYTES);

    const float scale = 0.08838834764831845f;  // 1/sqrt(128)
    const dim3 blk(256);

    // input conversions to bf16 hi/lo pairs (element counts / 4 for float4)
    convert_pair<<<592, 256>>>(x,  xh,  xl,  (size_t)NTOK * CDIM / 4);
    convert_pair<<<32,  256>>>(Wq, wqh, wql, (size_t)HDIM * CDIM / 4);
    convert_pair<<<32,  256>>>(Wk, wkh, wkl, (size_t)HDIM * CDIM / 4);
    convert_pair<<<256, 256>>>(Wv, wvh, wvl, (size_t)CDIM * CDIM / 4);
    convert_pair<<<256, 256>>>(Wo, woh, wol, (size_t)CDIM * CDIM / 4);

    // q = x @ Wq^T + bq -> pair (8192 x 128)
    gemm_mma<1><<<dim3(1, 64), blk, SMEM_BYTES>>>(xh, xl, wqh, wql, bq,
        nullptr, qh, ql, NTOK, HDIM, CDIM, HDIM);
    // k = x @ Wk^T + bk -> pair
    gemm_mma<1><<<dim3(1, 64), blk, SMEM_BYTES>>>(xh, xl, wkh, wkl, bk,
        nullptr, kh, kl, NTOK, HDIM, CDIM, HDIM);
    // v^T = (x @ Wv^T + bv)^T -> pair, stored [C, N]
    gemm_mma<2><<<dim3(8, 64), blk, SMEM_BYTES>>>(xh, xl, wvh, wvl, bv,
        nullptr, vth, vtl, NTOK, CDIM, CDIM, NTOK);
    // scores = q @ k^T -> fp32 (scale folded into softmax)
    gemm_mma<0><<<dim3(64, 64), blk, SMEM_BYTES>>>(qh, ql, kh, kl, nullptr,
        sc, nullptr, nullptr, NTOK, NTOK, HDIM, NTOK);
    // softmax rows -> attn pair
    softmax_pair<<<NTOK, 256>>>(sc, ah, al, NTOK, scale);
    // att = attn @ (v^T)^T -> pair (dominant GEMM, K=8192)
    gemm_mma<1><<<dim3(8, 64), blk, SMEM_BYTES>>>(ah, al, vth, vtl, nullptr,
        nullptr, oh, ol, NTOK, CDIM, NTOK, CDIM);
    // out = att @ Wo^T + bo -> fp32
    gemm_mma<0><<<dim3(8, 64), blk, SMEM_BYTES>>>(oh, ol, woh, wol, bo,
        out, nullptr, nullptr, NTOK, CDIM, CDIM, CDIM);
}

// round 13
// speedup vs baseline: 4.0789x; 1.2851x over previous
#include <cuda_runtime.h>
#include <cuda_bf16.h>
#include <cuda_fp16.h>
#include <cstdint>
#include <cstddef>

#define NTOK 8192
#define CDIM 1024
#define HDIM 128

// ======================= scratch (static, allocation-free) ==================
__device__ __align__(16) __nv_bfloat16 g_xh  [(size_t)NTOK * CDIM];
__device__ __align__(16) __nv_bfloat16 g_xl  [(size_t)NTOK * CDIM];
__device__ __align__(16) __nv_bfloat16 g_wqkh[2 * HDIM * CDIM];     // [Wq;Wk] pair
__device__ __align__(16) __nv_bfloat16 g_wqkl[2 * HDIM * CDIM];
__device__ float g_bqk[2 * HDIM];
__device__ __align__(16) __nv_bfloat16 g_wvh [CDIM * CDIM];
__device__ __align__(16) __nv_bfloat16 g_wvl [CDIM * CDIM];
__device__ __align__(16) __nv_bfloat16 g_woh [CDIM * CDIM];
__device__ __align__(16) __nv_bfloat16 g_wol [CDIM * CDIM];
__device__ __align__(16) __nv_bfloat16 g_qkh [(size_t)NTOK * 2 * HDIM]; // q|k pair
__device__ __align__(16) __nv_bfloat16 g_qkl [(size_t)NTOK * 2 * HDIM];
__device__ __align__(16) __half        g_vth [(size_t)CDIM * NTOK]; // v^T fp16 single
__device__ float g_sc[(size_t)NTOK * NTOK];                          // scores fp32
__device__ __align__(16) __half        g_ph  [(size_t)NTOK * NTOK]; // exp pair fp16
__device__ __align__(16) __half        g_pl  [(size_t)NTOK * NTOK];
__device__ float g_rinv[NTOK];                                       // 1/rowsum
__device__ __align__(16) __nv_bfloat16 g_oh  [(size_t)NTOK * CDIM]; // attn@v pair
__device__ __align__(16) __nv_bfloat16 g_ol  [(size_t)NTOK * CDIM];

// ======================= PTX helpers (sm_80+ portable only) =================
__device__ __forceinline__ uint32_t smem_u32(const void* p) {
    uint32_t a;
    asm("{ .reg .u64 t; cvta.to.shared.u64 t, %1; cvt.u32.u64 %0, t; }" : "=r"(a) : "l"(p));
    return a;
}
#define CP16(sm, gp) \
    asm volatile("cp.async.cg.shared.global [%0], [%1], 16;" :: "r"(sm), "l"(gp))
#define CP_COMMIT() asm volatile("cp.async.commit_group;" ::: "memory")
#define CP_WAIT1()  asm volatile("cp.async.wait_group 1;" ::: "memory")
#define CP_WAIT2()  asm volatile("cp.async.wait_group 2;" ::: "memory")

__device__ __forceinline__ void ldsm4(uint32_t& r0, uint32_t& r1, uint32_t& r2,
                                      uint32_t& r3, uint32_t a) {
    asm volatile("ldmatrix.sync.aligned.m8n8.x4.shared.b16 {%0,%1,%2,%3}, [%4];"
                 : "=r"(r0), "=r"(r1), "=r"(r2), "=r"(r3) : "r"(a));
}
__device__ __forceinline__ void mma16816(float* c, const uint32_t* a, const uint32_t* b) {
    asm volatile("mma.sync.aligned.m16n8k16.row.col.f32.bf16.bf16.f32 "
                 "{%0,%1,%2,%3}, {%4,%5,%6,%7}, {%8,%9}, {%0,%1,%2,%3};"
                 : "+f"(c[0]), "+f"(c[1]), "+f"(c[2]), "+f"(c[3])
                 : "r"(a[0]), "r"(a[1]), "r"(a[2]), "r"(a[3]), "r"(b[0]), "r"(b[1]));
}
__device__ __forceinline__ void mma16816h(float* c, const uint32_t* a, const uint32_t* b) {
    asm volatile("mma.sync.aligned.m16n8k16.row.col.f32.f16.f16.f32 "
                 "{%0,%1,%2,%3}, {%4,%5,%6,%7}, {%8,%9}, {%0,%1,%2,%3};"
                 : "+f"(c[0]), "+f"(c[1]), "+f"(c[2]), "+f"(c[3])
                 : "r"(a[0]), "r"(a[1]), "r"(a[2]), "r"(a[3]), "r"(b[0]), "r"(b[1]));
}

// FMA-pipe exp2: ~2.4e-6 max rel err, no MUFU.
__device__ __forceinline__ float fast_exp2(float y) {
    y = fmaxf(y, -120.f);
    const int   ni = __float2int_rn(y);
    const float f  = y - (float)ni;
    float p = 1.3333558146e-3f;
    p = fmaf(p, f, 9.6181291076e-3f);
    p = fmaf(p, f, 5.5504108664e-2f);
    p = fmaf(p, f, 2.4022650696e-1f);
    p = fmaf(p, f, 6.9314718056e-1f);
    p = fmaf(p, f, 1.0f);
    return p * __int_as_float((ni + 127) << 23);
}

#define SWZ(off) ((off) ^ (((off) >> 3) & 0x70))
static constexpr int BK   = 64;
static constexpr int MATB = 128 * 128;              // 16 KB tile (128 rows x 128B)

// ======================= bf16 3-term GEMM (split-bf16) ======================
// C = A @ B^T (+bias[col]).  A: M x K pair, B: N x K pair; ld = row stride.
// MODE 0: fp32 row-major   MODE 1: bf16 pair row-major
// MODE 3: fp16 SINGLE transposed C[col*ldc + row]
static constexpr int STAGES = 3;
static constexpr int STAGEB = 4 * MATB;             // 64 KB per stage
static constexpr int SMEM_BYTES = STAGES * STAGEB;  // 192 KB

template<int MODE>
__global__ __launch_bounds__(256, 1)
void gemm_mma(const __nv_bfloat16* __restrict__ Ah, const __nv_bfloat16* __restrict__ Al,
              const __nv_bfloat16* __restrict__ Bh, const __nv_bfloat16* __restrict__ Bl,
              const float* __restrict__ bias,
              float* __restrict__ Cf,
              __nv_bfloat16* __restrict__ Chi, __nv_bfloat16* __restrict__ Clo,
              int M, int N, int K, int ld, int ldc)
{
    extern __shared__ __align__(128) char smem[];
    const uint32_t sb = smem_u32(smem);

    const int tid  = threadIdx.x;
    const int lane = tid & 31;
    const int wid  = tid >> 5;
    const int warp_m = wid & 1;
    const int warp_n = wid >> 1;
    const int row0 = blockIdx.y * 128;
    const int col0 = blockIdx.x * 128;

    const __nv_bfloat16* mats[4] = {
        Ah + (size_t)row0 * ld, Al + (size_t)row0 * ld,
        Bh + (size_t)col0 * ld, Bl + (size_t)col0 * ld };
    const int mat = tid >> 6;
    const int lt  = tid & 63;
    const __nv_bfloat16* mbase = mats[mat];
    const uint32_t sm_mat = sb + (uint32_t)mat * MATB;

    auto load_stage = [&](int s, int buf) {
        const __nv_bfloat16* gp = mbase + (size_t)s * BK;
        const uint32_t sbuf = sm_mat + (uint32_t)buf * STAGEB;
        #pragma unroll
        for (int i = 0; i < 16; i++) {
            int c = i * 64 + lt;
            int r = c >> 3, g = c & 7;
            uint32_t off = (uint32_t)(r * 128 + g * 16);
            CP16(sbuf + SWZ(off), gp + (size_t)r * ld + g * 8);
        }
    };

    float acc[4][4][4];
    #pragma unroll
    for (int i = 0; i < 4; i++)
        #pragma unroll
        for (int j = 0; j < 4; j++)
            #pragma unroll
            for (int e = 0; e < 4; e++) acc[i][j][e] = 0.f;

    const int S = K / BK;
    load_stage(0, 0); CP_COMMIT();
    if (S > 1) load_stage(1, 1);
    CP_COMMIT();

    const int sel = lane >> 3, r8 = lane & 7;

    for (int s = 0; s < S; s++) {
        CP_WAIT1();
        __syncthreads();
        if (s + 2 < S) load_stage(s + 2, (s + 2) % STAGES);
        CP_COMMIT();

        const uint32_t stg = sb + (uint32_t)(s % STAGES) * STAGEB;
        const uint32_t Abh = stg, Abl = stg + MATB, Bbh = stg + 2 * MATB, Bbl = stg + 3 * MATB;

        #pragma unroll
        for (int kk = 0; kk < 4; kk++) {
            uint32_t ah[4][4], al[4][4], bh[2][4], bl[2][4];
            #pragma unroll
            for (int mt = 0; mt < 4; mt++) {
                int row = warp_m * 64 + mt * 16 + (sel & 1) * 8 + r8;
                int cidx = kk * 2 + (sel >> 1);
                uint32_t off = (uint32_t)(row * 128) + ((uint32_t)(cidx ^ (row & 7)) * 16);
                ldsm4(ah[mt][0], ah[mt][1], ah[mt][2], ah[mt][3], Abh + off);
                ldsm4(al[mt][0], al[mt][1], al[mt][2], al[mt][3], Abl + off);
            }
            #pragma unroll
            for (int nb = 0; nb < 2; nb++) {
                int n = warp_n * 32 + nb * 16 + (sel >> 1) * 8 + r8;
                int cidx = kk * 2 + (sel & 1);
                uint32_t off = (uint32_t)(n * 128) + ((uint32_t)(cidx ^ (n & 7)) * 16);
                ldsm4(bh[nb][0], bh[nb][1], bh[nb][2], bh[nb][3], Bbh + off);
                ldsm4(bl[nb][0], bl[nb][1], bl[nb][2], bl[nb][3], Bbl + off);
            }
            #pragma unroll
            for (int mt = 0; mt < 4; mt++)
                #pragma unroll
                for (int nt = 0; nt < 4; nt++) {
                    const uint32_t* bph = &bh[nt >> 1][(nt & 1) * 2];
                    const uint32_t* bpl = &bl[nt >> 1][(nt & 1) * 2];
                    mma16816(acc[mt][nt], ah[mt], bph);
                    mma16816(acc[mt][nt], ah[mt], bpl);
                    mma16816(acc[mt][nt], al[mt], bph);
                }
        }
    }
    __syncthreads();

    float* cs = (float*)smem;                   // 128 x 133 fp32
    const int g = lane >> 2, tq = lane & 3;
    #pragma unroll
    for (int mt = 0; mt < 4; mt++) {
        int rb = warp_m * 64 + mt * 16 + g;
        #pragma unroll
        for (int nt = 0; nt < 4; nt++) {
            int cb = warp_n * 32 + nt * 8 + tq * 2;
            cs[rb * 133 + cb]           = acc[mt][nt][0];
            cs[rb * 133 + cb + 1]       = acc[mt][nt][1];
            cs[(rb + 8) * 133 + cb]     = acc[mt][nt][2];
            cs[(rb + 8) * 133 + cb + 1] = acc[mt][nt][3];
        }
    }
    __syncthreads();

    if (MODE == 0) {
        const int col = tid & 127, half = tid >> 7;
        const float bv = bias ? __ldg(bias + col0 + col) : 0.f;
        for (int r = half; r < 128; r += 2)
            Cf[(size_t)(row0 + r) * ldc + col0 + col] = cs[r * 133 + col] + bv;
    } else if (MODE == 1) {
        const int col = tid & 127, half = tid >> 7;
        const float bv = bias ? __ldg(bias + col0 + col) : 0.f;
        for (int r = half; r < 128; r += 2) {
            float v = cs[r * 133 + col] + bv;
            __nv_bfloat16 h = __float2bfloat16(v);
            __nv_bfloat16 l = __float2bfloat16(v - __bfloat162float(h));
            size_t idx = (size_t)(row0 + r) * ldc + col0 + col;
            Chi[idx] = h; Clo[idx] = l;
        }
    } else {                                    // MODE 3: fp16 single, transposed
        __half* Hh = (__half*)Chi;
        const int row = tid & 127, half = tid >> 7;
        for (int c = half; c < 128; c += 2) {
            float v = cs[row * 133 + c] + (bias ? __ldg(bias + col0 + c) : 0.f);
            Hh[(size_t)(col0 + c) * ldc + row0 + row] = __float2half(v);
        }
    }
}

// ======================= fp16 attn@v GEMM: (Ph+Pl) @ Vh^T, 2 MMAs ===========
// A: M x K fp16 pair, B: N x K fp16 single; epilogue scales by rinv[row],
// writes bf16 pair row-major. 4-stage pipeline, 3 matrices x 16KB per stage.
static constexpr int AV_STAGES = 4;
static constexpr int AV_STAGEB = 3 * MATB;          // 48 KB
static constexpr int AV_SMEM   = AV_STAGES * AV_STAGEB;  // 192 KB

__global__ __launch_bounds__(256, 1)
void gemm_av(const __half* __restrict__ Ph, const __half* __restrict__ Pl,
             const __half* __restrict__ Vh, const float* __restrict__ rinv,
             __nv_bfloat16* __restrict__ Chi, __nv_bfloat16* __restrict__ Clo,
             int M, int N, int K, int ldc)
{
    extern __shared__ __align__(128) char smem[];
    const uint32_t sb = smem_u32(smem);

    const int tid  = threadIdx.x;
    const int lane = tid & 31;
    const int wid  = tid >> 5;
    const int warp_m = wid & 1;
    const int warp_n = wid >> 1;
    const int row0 = blockIdx.y * 128;
    const int col0 = blockIdx.x * 128;

    // loader: groups 0->Ph, 1->Pl, 2->Vh lower half, 3->Vh upper half
    const int grp = tid >> 6;
    const int lt  = tid & 63;
    const __half* gbase;
    uint32_t sm_mat; int c0, nch;
    if (grp == 0)      { gbase = Ph + (size_t)row0 * K; sm_mat = sb;            c0 = 0;   nch = 16; }
    else if (grp == 1) { gbase = Pl + (size_t)row0 * K; sm_mat = sb + MATB;     c0 = 0;   nch = 16; }
    else if (grp == 2) { gbase = Vh + (size_t)col0 * K; sm_mat = sb + 2 * MATB; c0 = 0;   nch = 8;  }
    else               { gbase = Vh + (size_t)col0 * K; sm_mat = sb + 2 * MATB; c0 = 512; nch = 8;  }

    auto load_stage = [&](int s, int buf) {
        const __half* gp = gbase + (size_t)s * BK;
        const uint32_t sbuf = sm_mat + (uint32_t)buf * AV_STAGEB;
        #pragma unroll
        for (int i = 0; i < 16; i++) {
            if (i >= nch) break;
            int c = c0 + i * 64 + lt;
            int r = c >> 3, g = c & 7;
            uint32_t off = (uint32_t)(r * 128 + g * 16);
            CP16(sbuf + SWZ(off), gp + (size_t)r * K + g * 8);
        }
    };

    float acc[4][4][4];
    #pragma unroll
    for (int i = 0; i < 4; i++)
        #pragma unroll
        for (int j = 0; j < 4; j++)
            #pragma unroll
            for (int e = 0; e < 4; e++) acc[i][j][e] = 0.f;

    const int S = K / BK;
    load_stage(0, 0); CP_COMMIT();
    load_stage(1, 1); CP_COMMIT();
    load_stage(2, 2); CP_COMMIT();

    const int sel = lane >> 3, r8 = lane & 7;

    for (int s = 0; s < S; s++) {
        CP_WAIT2();
        __syncthreads();
        if (s + 3 < S) load_stage(s + 3, (s + 3) % AV_STAGES);
        CP_COMMIT();

        const uint32_t stg = sb + (uint32_t)(s % AV_STAGES) * AV_STAGEB;
        const uint32_t Abh = stg, Abl = stg + MATB, Bb = stg + 2 * MATB;

        #pragma unroll
        for (int kk = 0; kk < 4; kk++) {
            uint32_t ph[4][4], pl[4][4], bh[2][4];
            #pragma unroll
            for (int mt = 0; mt < 4; mt++) {
                int row = warp_m * 64 + mt * 16 + (sel & 1) * 8 + r8;
                int cidx = kk * 2 + (sel >> 1);
                uint32_t off = (uint32_t)(row * 128) + ((uint32_t)(cidx ^ (row & 7)) * 16);
                ldsm4(ph[mt][0], ph[mt][1], ph[mt][2], ph[mt][3], Abh + off);
                ldsm4(pl[mt][0], pl[mt][1], pl[mt][2], pl[mt][3], Abl + off);
            }
            #pragma unroll
            for (int nb = 0; nb < 2; nb++) {
                int n = warp_n * 32 + nb * 16 + (sel >> 1) * 8 + r8;
                int cidx = kk * 2 + (sel & 1);
                uint32_t off = (uint32_t)(n * 128) + ((uint32_t)(cidx ^ (n & 7)) * 16);
                ldsm4(bh[nb][0], bh[nb][1], bh[nb][2], bh[nb][3], Bb + off);
            }
            #pragma unroll
            for (int mt = 0; mt < 4; mt++)
                #pragma unroll
                for (int nt = 0; nt < 4; nt++) {
                    const uint32_t* bp = &bh[nt >> 1][(nt & 1) * 2];
                    mma16816h(acc[mt][nt], ph[mt], bp);
                    mma16816h(acc[mt][nt], pl[mt], bp);
                }
        }
    }
    __syncthreads();

    float* cs = (float*)smem;
    const int g = lane >> 2, tq = lane & 3;
    #pragma unroll
    for (int mt = 0; mt < 4; mt++) {
        int rb = warp_m * 64 + mt * 16 + g;
        #pragma unroll
        for (int nt = 0; nt < 4; nt++) {
            int cb = warp_n * 32 + nt * 8 + tq * 2;
            cs[rb * 133 + cb]           = acc[mt][nt][0];
            cs[rb * 133 + cb + 1]       = acc[mt][nt][1];
            cs[(rb + 8) * 133 + cb]     = acc[mt][nt][2];
            cs[(rb + 8) * 133 + cb + 1] = acc[mt][nt][3];
        }
    }
    __syncthreads();

    const int col = tid & 127, half = tid >> 7;
    for (int r = half; r < 128; r += 2) {
        float v = cs[r * 133 + col] * __ldg(rinv + row0 + r);
        __nv_bfloat16 h = __float2bfloat16(v);
        __nv_bfloat16 l = __float2bfloat16(v - __bfloat162float(h));
        size_t idx = (size_t)(row0 + r) * ldc + col0 + col;
        Chi[idx] = h; Clo[idx] = l;
    }
}

// ======================= fp32 -> bf16 pair conversion (float4) ==============
__global__ __launch_bounds__(256)
void convert_pair(const float* __restrict__ s, __nv_bfloat16* __restrict__ h,
                  __nv_bfloat16* __restrict__ l, size_t n4)
{
    size_t i = (size_t)blockIdx.x * blockDim.x + threadIdx.x;
    const size_t stride = (size_t)gridDim.x * blockDim.x;
    for (; i < n4; i += stride) {
        float4 v = ((const float4*)s)[i];
        __nv_bfloat16 h0 = __float2bfloat16(v.x), h1 = __float2bfloat16(v.y);
        __nv_bfloat16 h2 = __float2bfloat16(v.z), h3 = __float2bfloat16(v.w);
        __nv_bfloat162 hp0 = {h0, h1}, hp1 = {h2, h3};
        __nv_bfloat162 lp0 = {__float2bfloat16(v.x - __bfloat162float(h0)),
                              __float2bfloat16(v.y - __bfloat162float(h1))};
        __nv_bfloat162 lp1 = {__float2bfloat16(v.z - __bfloat162float(h2)),
                              __float2bfloat16(v.w - __bfloat162float(h3))};
        ((__nv_bfloat162*)h)[i * 2]     = hp0;
        ((__nv_bfloat162*)h)[i * 2 + 1] = hp1;
        ((__nv_bfloat162*)l)[i * 2]     = lp0;
        ((__nv_bfloat162*)l)[i * 2 + 1] = lp1;
    }
}

__global__ void concat_bias(const float* a, const float* b, float* dst) {
    int t = threadIdx.x;                        // 256 threads
    dst[t] = (t < HDIM) ? a[t] : b[t - HDIM];
}

// ======= softmax: fp32 scores -> UNNORMALIZED fp16 pair + fp32 1/rowsum =====
__global__ __launch_bounds__(256)
void softmax_pair(const float* __restrict__ S, __half* __restrict__ Ph,
                  __half* __restrict__ Pl, float* __restrict__ rinv,
                  int n, float scale)
{
    __shared__ float red[256];
    const int tid = threadIdx.x;
    const float* row = S + (size_t)blockIdx.x * n;
    __half* oh = Ph + (size_t)blockIdx.x * n;
    __half* ol = Pl + (size_t)blockIdx.x * n;

    constexpr int PER = NTOK / 256;  // 32
    float v[PER];
    float mx = -1e30f;
    #pragma unroll
    for (int i = 0; i < PER; i++) {
        v[i] = row[i * 256 + tid];
        mx = fmaxf(mx, v[i]);
    }
    red[tid] = mx; __syncthreads();
    #pragma unroll
    for (int s = 128; s > 0; s >>= 1) {
        if (tid < s) red[tid] = fmaxf(red[tid], red[tid + s]);
        __syncthreads();
    }
    mx = red[0]; __syncthreads();

    const float k2 = scale * 1.4426950408889634f;
    float sum = 0.f;
    #pragma unroll
    for (int i = 0; i < PER; i++) {
        v[i] = fast_exp2((v[i] - mx) * k2);
        sum += v[i];
    }
    red[tid] = sum; __syncthreads();
    #pragma unroll
    for (int s = 128; s > 0; s >>= 1) {
        if (tid < s) red[tid] += red[tid + s];
        __syncthreads();
    }
    if (tid == 0) rinv[blockIdx.x] = 1.0f / red[0];

    #pragma unroll
    for (int i = 0; i < PER; i++) {
        __half h = __float2half(v[i]);
        oh[i * 256 + tid] = h;
        ol[i * 256 + tid] = __float2half(v[i] - __half2float(h));
    }
}

// ======================= launch =============================================
extern "C" void kernel_launch(void* const* d_in, const int* /*in_sizes*/, int /*n_in*/,
                              void* d_out, int /*out_size*/)
{
    const float* x  = (const float*)d_in[0];
    const float* Wq = (const float*)d_in[1];
    const float* bq = (const float*)d_in[2];
    const float* Wk = (const float*)d_in[3];
    const float* bk = (const float*)d_in[4];
    const float* Wv = (const float*)d_in[5];
    const float* bv = (const float*)d_in[6];
    const float* Wo = (const float*)d_in[7];
    const float* bo = (const float*)d_in[8];
    float* out = (float*)d_out;

    __nv_bfloat16 *xh, *xl, *wqkh, *wqkl, *wvh, *wvl, *woh, *wol;
    __nv_bfloat16 *qkh, *qkl, *oh, *ol;
    __half *vth, *ph, *pl;
    float *sc, *rinv, *bqk;
    cudaGetSymbolAddress((void**)&xh,   g_xh);   cudaGetSymbolAddress((void**)&xl,   g_xl);
    cudaGetSymbolAddress((void**)&wqkh, g_wqkh); cudaGetSymbolAddress((void**)&wqkl, g_wqkl);
    cudaGetSymbolAddress((void**)&wvh,  g_wvh);  cudaGetSymbolAddress((void**)&wvl,  g_wvl);
    cudaGetSymbolAddress((void**)&woh,  g_woh);  cudaGetSymbolAddress((void**)&wol,  g_wol);
    cudaGetSymbolAddress((void**)&qkh,  g_qkh);  cudaGetSymbolAddress((void**)&qkl,  g_qkl);
    cudaGetSymbolAddress((void**)&vth,  g_vth);
    cudaGetSymbolAddress((void**)&ph,   g_ph);   cudaGetSymbolAddress((void**)&pl,   g_pl);
    cudaGetSymbolAddress((void**)&oh,   g_oh);   cudaGetSymbolAddress((void**)&ol,   g_ol);
    cudaGetSymbolAddress((void**)&sc,   g_sc);   cudaGetSymbolAddress((void**)&rinv, g_rinv);
    cudaGetSymbolAddress((void**)&bqk,  g_bqk);

    cudaFuncSetAttribute(gemm_mma<0>, cudaFuncAttributeMaxDynamicSharedMemorySize, SMEM_BYTES);
    cudaFuncSetAttribute(gemm_mma<1>, cudaFuncAttributeMaxDynamicSharedMemorySize, SMEM_BYTES);
    cudaFuncSetAttribute(gemm_mma<3>, cudaFuncAttributeMaxDynamicSharedMemorySize, SMEM_BYTES);
    cudaFuncSetAttribute(gemm_av,     cudaFuncAttributeMaxDynamicSharedMemorySize, AV_SMEM);

    const float scale = 0.08838834764831845f;  // 1/sqrt(128)
    const dim3 blk(256);

    // input conversions
    convert_pair<<<592, 256>>>(x,  xh,  xl,  (size_t)NTOK * CDIM / 4);
    convert_pair<<<32,  256>>>(Wq, wqkh, wqkl, (size_t)HDIM * CDIM / 4);
    convert_pair<<<32,  256>>>(Wk, wqkh + (size_t)HDIM * CDIM,
                               wqkl + (size_t)HDIM * CDIM, (size_t)HDIM * CDIM / 4);
    convert_pair<<<256, 256>>>(Wv, wvh, wvl, (size_t)CDIM * CDIM / 4);
    convert_pair<<<256, 256>>>(Wo, woh, wol, (size_t)CDIM * CDIM / 4);
    concat_bias<<<1, 256>>>(bq, bk, bqk);

    // qk = x @ [Wq;Wk]^T + bqk -> bf16 pair, 8192 x 256
    gemm_mma<1><<<dim3(2, 64), blk, SMEM_BYTES>>>(xh, xl, wqkh, wqkl, bqk,
        nullptr, qkh, qkl, NTOK, 2 * HDIM, CDIM, CDIM, 2 * HDIM);
    // v^T = (x @ Wv^T + bv)^T -> fp16 single, stored [C, N]
    gemm_mma<3><<<dim3(8, 64), blk, SMEM_BYTES>>>(xh, xl, wvh, wvl, bv,
        nullptr, (__nv_bfloat16*)vth, nullptr, NTOK, CDIM, CDIM, CDIM, NTOK);
    // scores = q @ k^T -> fp32 (q = qk cols 0..127, k = qk cols 128..255)
    gemm_mma<0><<<dim3(64, 64), blk, SMEM_BYTES>>>(qkh, qkl, qkh + HDIM, qkl + HDIM,
        nullptr, sc, nullptr, nullptr, NTOK, NTOK, HDIM, 2 * HDIM, NTOK);
    // softmax rows -> unnormalized fp16 pair + 1/rowsum
    softmax_pair<<<NTOK, 256>>>(sc, ph, pl, rinv, NTOK, scale);
    // att = (P @ v) * rinv -> bf16 pair   (dominant GEMM, 2 MMAs/tile)
    gemm_av<<<dim3(8, 64), blk, AV_SMEM>>>(ph, pl, vth, rinv,
        oh, ol, NTOK, CDIM, NTOK, CDIM);
    // out = att @ Wo^T + bo -> fp32
    gemm_mma<0><<<dim3(8, 64), blk, SMEM_BYTES>>>(oh, ol, woh, wol, bo,
        out, nullptr, nullptr, NTOK, CDIM, CDIM, CDIM, CDIM);
}

// round 14
// speedup vs baseline: 5.2890x; 1.2967x over previous
#include <cuda_runtime.h>
#include <cuda_fp16.h>
#include <cstdint>
#include <cstddef>

#define NTOK 8192
#define CDIM 1024
#define HDIM 128

// ======================= scratch (static, allocation-free) ==================
__device__ __align__(16) __half g_xh  [(size_t)NTOK * CDIM];
__device__ __align__(16) __half g_xl  [(size_t)NTOK * CDIM];
__device__ __align__(16) __half g_wqkh[2 * HDIM * CDIM];     // [Wq;Wk] pair
__device__ __align__(16) __half g_wqkl[2 * HDIM * CDIM];
__device__ float g_bqk[2 * HDIM];
__device__ __align__(16) __half g_wvh [CDIM * CDIM];
__device__ __align__(16) __half g_wvl [CDIM * CDIM];
__device__ __align__(16) __half g_woh [CDIM * CDIM];
__device__ __align__(16) __half g_wol [CDIM * CDIM];
__device__ __align__(16) __half g_qkh [(size_t)NTOK * 2 * HDIM]; // q|k pair
__device__ __align__(16) __half g_qkl [(size_t)NTOK * 2 * HDIM];
__device__ __align__(16) __half g_vth [(size_t)CDIM * NTOK];     // v^T fp16 single
__device__ float g_sc[(size_t)NTOK * NTOK];                      // scores fp32
__device__ __align__(16) __half g_ph  [(size_t)NTOK * NTOK];     // exp fp16 single
__device__ float g_rinv[NTOK];                                   // 1/rowsum
__device__ __align__(16) __half g_oh  [(size_t)NTOK * CDIM];     // attn@v pair
__device__ __align__(16) __half g_ol  [(size_t)NTOK * CDIM];

// ======================= PTX helpers (sm_80+ portable only) =================
__device__ __forceinline__ uint32_t smem_u32(const void* p) {
    uint32_t a;
    asm("{ .reg .u64 t; cvta.to.shared.u64 t, %1; cvt.u32.u64 %0, t; }" : "=r"(a) : "l"(p));
    return a;
}
#define CP16(sm, gp) \
    asm volatile("cp.async.cg.shared.global [%0], [%1], 16;" :: "r"(sm), "l"(gp))
#define CP_COMMIT() asm volatile("cp.async.commit_group;" ::: "memory")

__device__ __forceinline__ void ldsm4(uint32_t& r0, uint32_t& r1, uint32_t& r2,
                                      uint32_t& r3, uint32_t a) {
    asm volatile("ldmatrix.sync.aligned.m8n8.x4.shared.b16 {%0,%1,%2,%3}, [%4];"
                 : "=r"(r0), "=r"(r1), "=r"(r2), "=r"(r3) : "r"(a));
}
__device__ __forceinline__ void mma16816h(float* c, const uint32_t* a, const uint32_t* b) {
    asm volatile("mma.sync.aligned.m16n8k16.row.col.f32.f16.f16.f32 "
                 "{%0,%1,%2,%3}, {%4,%5,%6,%7}, {%8,%9}, {%0,%1,%2,%3};"
                 : "+f"(c[0]), "+f"(c[1]), "+f"(c[2]), "+f"(c[3])
                 : "r"(a[0]), "r"(a[1]), "r"(a[2]), "r"(a[3]), "r"(b[0]), "r"(b[1]));
}

// FMA-pipe exp2: ~2.4e-6 max rel err, no MUFU.
__device__ __forceinline__ float fast_exp2(float y) {
    y = fmaxf(y, -120.f);
    const int   ni = __float2int_rn(y);
    const float f  = y - (float)ni;
    float p = 1.3333558146e-3f;
    p = fmaf(p, f, 9.6181291076e-3f);
    p = fmaf(p, f, 5.5504108664e-2f);
    p = fmaf(p, f, 2.4022650696e-1f);
    p = fmaf(p, f, 6.9314718056e-1f);
    p = fmaf(p, f, 1.0f);
    return p * __int_as_float((ni + 127) << 23);
}

#define SWZ(off) ((off) ^ (((off) >> 3) & 0x70))
static constexpr int BK   = 64;
static constexpr int MATB = 128 * 128;              // 16 KB tile (128 rows x 128B)
static constexpr int SMEM_MAX = 192 * 1024;

// ======================= unified fp16 GEMM ==================================
// C = A @ B^T (+bias[col]) (*rinv[row]).  A: M x K, B: N x K.
// NMMA 3: A pair x B pair (hh + hl + lh)   NMMA 2: A pair x B single
// NMMA 1: A single x B single
// MODE 0: fp32 row-major   MODE 1: fp16 pair row-major   MODE 2: fp16 single,
// transposed C[col*ldc + row].
// BM=BN=128, BK=64, 256 threads (8 warps, 64x32 warp tiles). Pipeline depth
// scales with matrices/stage: 4 mats->3 stages, 3->4, 2->6 (192 KB total).
template<int NMMA, int MODE>
__global__ __launch_bounds__(256, 1)
void gemm_h(const __half* __restrict__ Ah, const __half* __restrict__ Al,
            const __half* __restrict__ Bh, const __half* __restrict__ Bl,
            const float* __restrict__ bias, const float* __restrict__ rinv,
            float* __restrict__ Cf, __half* __restrict__ Ch, __half* __restrict__ Cl,
            int M, int N, int K, int lda, int ldb, int ldc)
{
    constexpr int NMAT = (NMMA == 3) ? 4 : (NMMA == 2) ? 3 : 2;
    constexpr int STG  = (NMMA == 3) ? 3 : (NMMA == 2) ? 4 : 6;
    constexpr int STB  = NMAT * MATB;

    extern __shared__ __align__(128) char smem[];
    const uint32_t sb = smem_u32(smem);

    const int tid  = threadIdx.x;
    const int lane = tid & 31;
    const int wid  = tid >> 5;
    const int warp_m = wid & 1;
    const int warp_n = wid >> 1;
    const int row0 = blockIdx.y * 128;
    const int col0 = blockIdx.x * 128;

    // ---- loader groups: 4 x 64 threads ------------------------------------
    const int grp = tid >> 6, lt = tid & 63;
    const __half* gbase; uint32_t smoff; int c0, nch, gld;
    if (NMMA == 3) {
        const __half* gs[4] = {Ah + (size_t)row0 * lda, Al + (size_t)row0 * lda,
                               Bh + (size_t)col0 * ldb, Bl + (size_t)col0 * ldb};
        gbase = gs[grp]; smoff = (uint32_t)grp * MATB; c0 = 0; nch = 16;
        gld = (grp < 2) ? lda : ldb;
    } else if (NMMA == 2) {
        if (grp == 0)      { gbase = Ah + (size_t)row0 * lda; smoff = 0;        c0 = 0;   nch = 16; gld = lda; }
        else if (grp == 1) { gbase = Al + (size_t)row0 * lda; smoff = MATB;     c0 = 0;   nch = 16; gld = lda; }
        else if (grp == 2) { gbase = Bh + (size_t)col0 * ldb; smoff = 2 * MATB; c0 = 0;   nch = 8;  gld = ldb; }
        else               { gbase = Bh + (size_t)col0 * ldb; smoff = 2 * MATB; c0 = 512; nch = 8;  gld = ldb; }
    } else {
        if (grp == 0)      { gbase = Ah + (size_t)row0 * lda; smoff = 0;    c0 = 0;   nch = 8; gld = lda; }
        else if (grp == 1) { gbase = Ah + (size_t)row0 * lda; smoff = 0;    c0 = 512; nch = 8; gld = lda; }
        else if (grp == 2) { gbase = Bh + (size_t)col0 * ldb; smoff = MATB; c0 = 0;   nch = 8; gld = ldb; }
        else               { gbase = Bh + (size_t)col0 * ldb; smoff = MATB; c0 = 512; nch = 8; gld = ldb; }
    }

    auto load_stage = [&](int s, int buf) {
        const __half* gp = gbase + (size_t)s * BK;
        const uint32_t sbuf = sb + smoff + (uint32_t)buf * STB;
        #pragma unroll
        for (int i = 0; i < 16; i++) {
            if (i >= nch) break;
            int c = c0 + i * 64 + lt;
            int r = c >> 3, g = c & 7;
            uint32_t off = (uint32_t)(r * 128 + g * 16);
            CP16(sbuf + SWZ(off), gp + (size_t)r * gld + g * 8);
        }
    };

    float acc[4][4][4];
    #pragma unroll
    for (int i = 0; i < 4; i++)
        #pragma unroll
        for (int j = 0; j < 4; j++)
            #pragma unroll
            for (int e = 0; e < 4; e++) acc[i][j][e] = 0.f;

    const int S = K / BK;
    #pragma unroll
    for (int i = 0; i < STG - 1; i++) {
        if (i < S) load_stage(i, i);
        CP_COMMIT();
    }

    const int sel = lane >> 3, r8 = lane & 7;

    for (int s = 0; s < S; s++) {
        asm volatile("cp.async.wait_group %0;" :: "n"(STG - 2) : "memory");
        __syncthreads();
        if (s + STG - 1 < S) load_stage(s + STG - 1, (s + STG - 1) % STG);
        CP_COMMIT();

        const uint32_t stg = sb + (uint32_t)(s % STG) * STB;
        const uint32_t Abh = stg;
        const uint32_t Abl = stg + MATB;                       // NMMA>=2
        const uint32_t Bbh = stg + (NMAT - (NMMA == 3 ? 2 : 1)) * MATB;
        const uint32_t Bbl = stg + 3 * MATB;                   // NMMA==3

        #pragma unroll
        for (int kk = 0; kk < 4; kk++) {
            uint32_t ah[4][4], al[4][4], bh[2][4], bl[2][4];
            #pragma unroll
            for (int mt = 0; mt < 4; mt++) {
                int row = warp_m * 64 + mt * 16 + (sel & 1) * 8 + r8;
                int cidx = kk * 2 + (sel >> 1);
                uint32_t off = (uint32_t)(row * 128) + ((uint32_t)(cidx ^ (row & 7)) * 16);
                ldsm4(ah[mt][0], ah[mt][1], ah[mt][2], ah[mt][3], Abh + off);
                if (NMMA >= 2)
                    ldsm4(al[mt][0], al[mt][1], al[mt][2], al[mt][3], Abl + off);
            }
            #pragma unroll
            for (int nb = 0; nb < 2; nb++) {
                int n = warp_n * 32 + nb * 16 + (sel >> 1) * 8 + r8;
                int cidx = kk * 2 + (sel & 1);
                uint32_t off = (uint32_t)(n * 128) + ((uint32_t)(cidx ^ (n & 7)) * 16);
                ldsm4(bh[nb][0], bh[nb][1], bh[nb][2], bh[nb][3], Bbh + off);
                if (NMMA == 3)
                    ldsm4(bl[nb][0], bl[nb][1], bl[nb][2], bl[nb][3], Bbl + off);
            }
            #pragma unroll
            for (int mt = 0; mt < 4; mt++)
                #pragma unroll
                for (int nt = 0; nt < 4; nt++) {
                    const uint32_t* bph = &bh[nt >> 1][(nt & 1) * 2];
                    mma16816h(acc[mt][nt], ah[mt], bph);
                    if (NMMA == 3) {
                        const uint32_t* bpl = &bl[nt >> 1][(nt & 1) * 2];
                        mma16816h(acc[mt][nt], ah[mt], bpl);
                    }
                    if (NMMA >= 2)
                        mma16816h(acc[mt][nt], al[mt], bph);
                }
        }
    }
    __syncthreads();

    // ---- epilogue: frags -> padded SMEM fp32 -> coalesced global ----------
    float* cs = (float*)smem;                   // 128 x 133 fp32 (68 KB)
    const int g = lane >> 2, tq = lane & 3;
    #pragma unroll
    for (int mt = 0; mt < 4; mt++) {
        int rb = warp_m * 64 + mt * 16 + g;
        #pragma unroll
        for (int nt = 0; nt < 4; nt++) {
            int cb = warp_n * 32 + nt * 8 + tq * 2;
            cs[rb * 133 + cb]           = acc[mt][nt][0];
            cs[rb * 133 + cb + 1]       = acc[mt][nt][1];
            cs[(rb + 8) * 133 + cb]     = acc[mt][nt][2];
            cs[(rb + 8) * 133 + cb + 1] = acc[mt][nt][3];
        }
    }
    __syncthreads();

    if (MODE == 0) {
        const int col = tid & 127, half = tid >> 7;
        const float bv = bias ? __ldg(bias + col0 + col) : 0.f;
        for (int r = half; r < 128; r += 2)
            Cf[(size_t)(row0 + r) * ldc + col0 + col] = cs[r * 133 + col] + bv;
    } else if (MODE == 1) {
        const int col = tid & 127, half = tid >> 7;
        const float bv = bias ? __ldg(bias + col0 + col) : 0.f;
        for (int r = half; r < 128; r += 2) {
            float v = cs[r * 133 + col] + bv;
            if (rinv) v *= __ldg(rinv + row0 + r);
            __half h = __float2half(v);
            size_t idx = (size_t)(row0 + r) * ldc + col0 + col;
            Ch[idx] = h;
            Cl[idx] = __float2half(v - __half2float(h));
        }
    } else {                                    // MODE 2: fp16 single, transposed
        const int row = tid & 127, half = tid >> 7;
        for (int c = half; c < 128; c += 2) {
            float v = cs[row * 133 + c] + (bias ? __ldg(bias + col0 + c) : 0.f);
            Ch[(size_t)(col0 + c) * ldc + row0 + row] = __float2half(v);
        }
    }
}

// ======================= fp32 -> fp16 pair conversion (float4) ==============
__global__ __launch_bounds__(256)
void convert_pair(const float* __restrict__ s, __half* __restrict__ h,
                  __half* __restrict__ l, size_t n4)
{
    size_t i = (size_t)blockIdx.x * blockDim.x + threadIdx.x;
    const size_t stride = (size_t)gridDim.x * blockDim.x;
    for (; i < n4; i += stride) {
        float4 v = ((const float4*)s)[i];
        __half h0 = __float2half(v.x), h1 = __float2half(v.y);
        __half h2 = __float2half(v.z), h3 = __float2half(v.w);
        __half2 hp0 = {h0, h1}, hp1 = {h2, h3};
        __half2 lp0 = {__float2half(v.x - __half2float(h0)),
                       __float2half(v.y - __half2float(h1))};
        __half2 lp1 = {__float2half(v.z - __half2float(h2)),
                       __float2half(v.w - __half2float(h3))};
        ((__half2*)h)[i * 2]     = hp0;
        ((__half2*)h)[i * 2 + 1] = hp1;
        ((__half2*)l)[i * 2]     = lp0;
        ((__half2*)l)[i * 2 + 1] = lp1;
    }
}

__global__ void concat_bias(const float* a, const float* b, float* dst) {
    int t = threadIdx.x;                        // 256 threads
    dst[t] = (t < HDIM) ? a[t] : b[t - HDIM];
}

// ======= softmax: fp32 scores -> UNNORMALIZED fp16 single + fp32 1/rowsum ===
__global__ __launch_bounds__(256)
void softmax_h(const float* __restrict__ S, __half* __restrict__ Ph,
               float* __restrict__ rinv, int n, float scale)
{
    __shared__ float red[256];
    const int tid = threadIdx.x;
    const float* row = S + (size_t)blockIdx.x * n;
    __half* oh = Ph + (size_t)blockIdx.x * n;

    constexpr int PER = NTOK / 256;  // 32
    float v[PER];
    float mx = -1e30f;
    #pragma unroll
    for (int i = 0; i < PER; i++) {
        v[i] = row[i * 256 + tid];
        mx = fmaxf(mx, v[i]);
    }
    red[tid] = mx; __syncthreads();
    #pragma unroll
    for (int s = 128; s > 0; s >>= 1) {
        if (tid < s) red[tid] = fmaxf(red[tid], red[tid + s]);
        __syncthreads();
    }
    mx = red[0]; __syncthreads();

    const float k2 = scale * 1.4426950408889634f;
    float sum = 0.f;
    #pragma unroll
    for (int i = 0; i < PER; i++) {
        v[i] = fast_exp2((v[i] - mx) * k2);
        sum += v[i];
    }
    red[tid] = sum; __syncthreads();
    #pragma unroll
    for (int s = 128; s > 0; s >>= 1) {
        if (tid < s) red[tid] += red[tid + s];
        __syncthreads();
    }
    if (tid == 0) rinv[blockIdx.x] = 1.0f / red[0];

    #pragma unroll
    for (int i = 0; i < PER; i++)
        oh[i * 256 + tid] = __float2half(v[i]);
}

// ======================= launch =============================================
extern "C" void kernel_launch(void* const* d_in, const int* /*in_sizes*/, int /*n_in*/,
                              void* d_out, int /*out_size*/)
{
    const float* x  = (const float*)d_in[0];
    const float* Wq = (const float*)d_in[1];
    const float* bq = (const float*)d_in[2];
    const float* Wk = (const float*)d_in[3];
    const float* bk = (const float*)d_in[4];
    const float* Wv = (const float*)d_in[5];
    const float* bv = (const float*)d_in[6];
    const float* Wo = (const float*)d_in[7];
    const float* bo = (const float*)d_in[8];
    float* out = (float*)d_out;

    __half *xh, *xl, *wqkh, *wqkl, *wvh, *wvl, *woh, *wol;
    __half *qkh, *qkl, *vth, *ph, *oh, *ol;
    float *sc, *rinv, *bqk;
    cudaGetSymbolAddress((void**)&xh,   g_xh);   cudaGetSymbolAddress((void**)&xl,   g_xl);
    cudaGetSymbolAddress((void**)&wqkh, g_wqkh); cudaGetSymbolAddress((void**)&wqkl, g_wqkl);
    cudaGetSymbolAddress((void**)&wvh,  g_wvh);  cudaGetSymbolAddress((void**)&wvl,  g_wvl);
    cudaGetSymbolAddress((void**)&woh,  g_woh);  cudaGetSymbolAddress((void**)&wol,  g_wol);
    cudaGetSymbolAddress((void**)&qkh,  g_qkh);  cudaGetSymbolAddress((void**)&qkl,  g_qkl);
    cudaGetSymbolAddress((void**)&vth,  g_vth);  cudaGetSymbolAddress((void**)&ph,   g_ph);
    cudaGetSymbolAddress((void**)&oh,   g_oh);   cudaGetSymbolAddress((void**)&ol,   g_ol);
    cudaGetSymbolAddress((void**)&sc,   g_sc);   cudaGetSymbolAddress((void**)&rinv, g_rinv);
    cudaGetSymbolAddress((void**)&bqk,  g_bqk);

    cudaFuncSetAttribute(gemm_h<3,1>, cudaFuncAttributeMaxDynamicSharedMemorySize, SMEM_MAX);
    cudaFuncSetAttribute(gemm_h<3,2>, cudaFuncAttributeMaxDynamicSharedMemorySize, SMEM_MAX);
    cudaFuncSetAttribute(gemm_h<3,0>, cudaFuncAttributeMaxDynamicSharedMemorySize, SMEM_MAX);
    cudaFuncSetAttribute(gemm_h<1,1>, cudaFuncAttributeMaxDynamicSharedMemorySize, SMEM_MAX);
    cudaFuncSetAttribute(gemm_h<2,0>, cudaFuncAttributeMaxDynamicSharedMemorySize, SMEM_MAX);

    const float scale = 0.08838834764831845f;  // 1/sqrt(128)
    const dim3 blk(256);

    // input conversions to fp16 hi/lo pairs
    convert_pair<<<592, 256>>>(x,  xh,  xl,  (size_t)NTOK * CDIM / 4);
    convert_pair<<<32,  256>>>(Wq, wqkh, wqkl, (size_t)HDIM * CDIM / 4);
    convert_pair<<<32,  256>>>(Wk, wqkh + (size_t)HDIM * CDIM,
                               wqkl + (size_t)HDIM * CDIM, (size_t)HDIM * CDIM / 4);
    convert_pair<<<256, 256>>>(Wv, wvh, wvl, (size_t)CDIM * CDIM / 4);
    convert_pair<<<256, 256>>>(Wo, woh, wol, (size_t)CDIM * CDIM / 4);
    concat_bias<<<1, 256>>>(bq, bk, bqk);

    // qk = x @ [Wq;Wk]^T + bqk -> fp16 pair, 8192 x 256   (3-term)
    gemm_h<3,1><<<dim3(2, 64), blk, SMEM_MAX>>>(xh, xl, wqkh, wqkl, bqk, nullptr,
        nullptr, qkh, qkl, NTOK, 2 * HDIM, CDIM, CDIM, CDIM, 2 * HDIM);
    // v^T = (x @ Wv^T + bv)^T -> fp16 single, stored [C, N]   (3-term)
    gemm_h<3,2><<<dim3(8, 64), blk, SMEM_MAX>>>(xh, xl, wvh, wvl, bv, nullptr,
        nullptr, vth, nullptr, NTOK, CDIM, CDIM, CDIM, CDIM, NTOK);
    // scores = q @ k^T -> fp32   (3-term; q/k are slices of qk, ld=256)
    gemm_h<3,0><<<dim3(64, 64), blk, SMEM_MAX>>>(qkh, qkl, qkh + HDIM, qkl + HDIM,
        nullptr, nullptr, sc, nullptr, nullptr, NTOK, NTOK, HDIM, 2 * HDIM, 2 * HDIM, NTOK);
    // softmax rows -> unnormalized fp16 single + 1/rowsum
    softmax_h<<<NTOK, 256>>>(sc, ph, rinv, NTOK, scale);
    // att = (P @ v) * rinv -> fp16 pair   (dominant GEMM, 1 MMA/tile)
    gemm_h<1,1><<<dim3(8, 64), blk, SMEM_MAX>>>(ph, nullptr, vth, nullptr,
        nullptr, rinv, nullptr, oh, ol, NTOK, CDIM, NTOK, NTOK, NTOK, CDIM);
    // out = att @ Wo^T + bo -> fp32   (2-term: att pair x Wo single)
    gemm_h<2,0><<<dim3(8, 64), blk, SMEM_MAX>>>(oh, ol, woh, nullptr, bo, nullptr,
        out, nullptr, nullptr, NTOK, CDIM, CDIM, CDIM, CDIM, CDIM);
}

// round 15
// speedup vs baseline: 5.8408x; 1.1043x over previous
#include <cuda_runtime.h>
#include <cuda_fp16.h>
#include <cstdint>
#include <cstddef>

#define NTOK 8192
#define CDIM 1024
#define HDIM 128

// ======================= scratch (static, allocation-free) ==================
__device__ __align__(16) __half g_xh  [(size_t)NTOK * CDIM];
__device__ __align__(16) __half g_xl  [(size_t)NTOK * CDIM];
__device__ __align__(16) __half g_wqkh[2 * HDIM * CDIM];     // [Wq;Wk] pair
__device__ __align__(16) __half g_wqkl[2 * HDIM * CDIM];
__device__ float g_bqk[2 * HDIM];
__device__ __align__(16) __half g_wvh [CDIM * CDIM];         // Wv fp16 single
__device__ __align__(16) __half g_woh [CDIM * CDIM];         // Wo fp16 single
__device__ __align__(16) __half g_qkh [(size_t)NTOK * 2 * HDIM]; // q|k pair
__device__ __align__(16) __half g_qkl [(size_t)NTOK * 2 * HDIM];
__device__ __align__(16) __half g_vth [(size_t)CDIM * NTOK];     // v^T fp16 single
__device__ float g_sc[(size_t)NTOK * NTOK];                      // scores fp32
__device__ __align__(16) __half g_ph  [(size_t)NTOK * NTOK];     // exp fp16 single
__device__ float g_rinv[NTOK];                                   // 1/rowsum
__device__ __align__(16) __half g_oh  [(size_t)NTOK * CDIM];     // attn@v fp16 single

// ======================= PTX helpers (sm_80+ portable only) =================
__device__ __forceinline__ uint32_t smem_u32(const void* p) {
    uint32_t a;
    asm("{ .reg .u64 t; cvta.to.shared.u64 t, %1; cvt.u32.u64 %0, t; }" : "=r"(a) : "l"(p));
    return a;
}
#define CP16(sm, gp) \
    asm volatile("cp.async.cg.shared.global [%0], [%1], 16;" :: "r"(sm), "l"(gp))
#define CP_COMMIT() asm volatile("cp.async.commit_group;" ::: "memory")

__device__ __forceinline__ void ldsm4(uint32_t& r0, uint32_t& r1, uint32_t& r2,
                                      uint32_t& r3, uint32_t a) {
    asm volatile("ldmatrix.sync.aligned.m8n8.x4.shared.b16 {%0,%1,%2,%3}, [%4];"
                 : "=r"(r0), "=r"(r1), "=r"(r2), "=r"(r3) : "r"(a));
}
__device__ __forceinline__ void mma16816h(float* c, const uint32_t* a, const uint32_t* b) {
    asm volatile("mma.sync.aligned.m16n8k16.row.col.f32.f16.f16.f32 "
                 "{%0,%1,%2,%3}, {%4,%5,%6,%7}, {%8,%9}, {%0,%1,%2,%3};"
                 : "+f"(c[0]), "+f"(c[1]), "+f"(c[2]), "+f"(c[3])
                 : "r"(a[0]), "r"(a[1]), "r"(a[2]), "r"(a[3]), "r"(b[0]), "r"(b[1]));
}

// FMA-pipe exp2: ~2.4e-6 max rel err, no MUFU.
__device__ __forceinline__ float fast_exp2(float y) {
    y = fmaxf(y, -120.f);
    const int   ni = __float2int_rn(y);
    const float f  = y - (float)ni;
    float p = 1.3333558146e-3f;
    p = fmaf(p, f, 9.6181291076e-3f);
    p = fmaf(p, f, 5.5504108664e-2f);
    p = fmaf(p, f, 2.4022650696e-1f);
    p = fmaf(p, f, 6.9314718056e-1f);
    p = fmaf(p, f, 1.0f);
    return p * __int_as_float((ni + 127) << 23);
}

#define SWZ(off) ((off) ^ (((off) >> 3) & 0x70))
static constexpr int BK   = 64;
static constexpr int MATB = 128 * 128;              // 16 KB tile (128 rows x 128B)
static constexpr int SMEM_MAX = 192 * 1024;

// ======================= unified fp16 GEMM ==================================
// C = A @ B^T (+bias[col]) (*rinv[row]).  A: M x K, B: N x K.
// NMMA 3: A pair x B pair (hh + hl + lh)   NMMA 2: A pair x B single
// NMMA 1: A single x B single
// MODE 0: fp32 row-major + bias           MODE 1: fp16 pair row-major + bias
// MODE 2: fp16 single transposed + bias   MODE 3: fp16 single row-major * rinv
// BM=BN=128, BK=64, 256 threads (8 warps, 64x32 warp tiles). Pipeline depth
// scales with matrices/stage: 4 mats->3 stages, 3->4, 2->6 (192 KB total).
template<int NMMA, int MODE>
__global__ __launch_bounds__(256, 1)
void gemm_h(const __half* __restrict__ Ah, const __half* __restrict__ Al,
            const __half* __restrict__ Bh, const __half* __restrict__ Bl,
            const float* __restrict__ bias, const float* __restrict__ rinv,
            float* __restrict__ Cf, __half* __restrict__ Ch, __half* __restrict__ Cl,
            int M, int N, int K, int lda, int ldb, int ldc)
{
    constexpr int NMAT = (NMMA == 3) ? 4 : (NMMA == 2) ? 3 : 2;
    constexpr int STG  = (NMMA == 3) ? 3 : (NMMA == 2) ? 4 : 6;
    constexpr int STB  = NMAT * MATB;

    extern __shared__ __align__(128) char smem[];
    const uint32_t sb = smem_u32(smem);

    const int tid  = threadIdx.x;
    const int lane = tid & 31;
    const int wid  = tid >> 5;
    const int warp_m = wid & 1;
    const int warp_n = wid >> 1;
    const int row0 = blockIdx.y * 128;
    const int col0 = blockIdx.x * 128;

    // ---- loader groups: 4 x 64 threads ------------------------------------
    const int grp = tid >> 6, lt = tid & 63;
    const __half* gbase; uint32_t smoff; int c0, nch, gld;
    if (NMMA == 3) {
        const __half* gs[4] = {Ah + (size_t)row0 * lda, Al + (size_t)row0 * lda,
                               Bh + (size_t)col0 * ldb, Bl + (size_t)col0 * ldb};
        gbase = gs[grp]; smoff = (uint32_t)grp * MATB; c0 = 0; nch = 16;
        gld = (grp < 2) ? lda : ldb;
    } else if (NMMA == 2) {
        if (grp == 0)      { gbase = Ah + (size_t)row0 * lda; smoff = 0;        c0 = 0;   nch = 16; gld = lda; }
        else if (grp == 1) { gbase = Al + (size_t)row0 * lda; smoff = MATB;     c0 = 0;   nch = 16; gld = lda; }
        else if (grp == 2) { gbase = Bh + (size_t)col0 * ldb; smoff = 2 * MATB; c0 = 0;   nch = 8;  gld = ldb; }
        else               { gbase = Bh + (size_t)col0 * ldb; smoff = 2 * MATB; c0 = 512; nch = 8;  gld = ldb; }
    } else {
        if (grp == 0)      { gbase = Ah + (size_t)row0 * lda; smoff = 0;    c0 = 0;   nch = 8; gld = lda; }
        else if (grp == 1) { gbase = Ah + (size_t)row0 * lda; smoff = 0;    c0 = 512; nch = 8; gld = lda; }
        else if (grp == 2) { gbase = Bh + (size_t)col0 * ldb; smoff = MATB; c0 = 0;   nch = 8; gld = ldb; }
        else               { gbase = Bh + (size_t)col0 * ldb; smoff = MATB; c0 = 512; nch = 8; gld = ldb; }
    }

    auto load_stage = [&](int s, int buf) {
        const __half* gp = gbase + (size_t)s * BK;
        const uint32_t sbuf = sb + smoff + (uint32_t)buf * STB;
        #pragma unroll
        for (int i = 0; i < 16; i++) {
            if (i >= nch) break;
            int c = c0 + i * 64 + lt;
            int r = c >> 3, g = c & 7;
            uint32_t off = (uint32_t)(r * 128 + g * 16);
            CP16(sbuf + SWZ(off), gp + (size_t)r * gld + g * 8);
        }
    };

    float acc[4][4][4];
    #pragma unroll
    for (int i = 0; i < 4; i++)
        #pragma unroll
        for (int j = 0; j < 4; j++)
            #pragma unroll
            for (int e = 0; e < 4; e++) acc[i][j][e] = 0.f;

    const int S = K / BK;
    #pragma unroll
    for (int i = 0; i < STG - 1; i++) {
        if (i < S) load_stage(i, i);
        CP_COMMIT();
    }

    const int sel = lane >> 3, r8 = lane & 7;

    for (int s = 0; s < S; s++) {
        asm volatile("cp.async.wait_group %0;" :: "n"(STG - 2) : "memory");
        __syncthreads();
        if (s + STG - 1 < S) load_stage(s + STG - 1, (s + STG - 1) % STG);
        CP_COMMIT();

        const uint32_t stg = sb + (uint32_t)(s % STG) * STB;
        const uint32_t Abh = stg;
        const uint32_t Abl = stg + MATB;                       // NMMA>=2
        const uint32_t Bbh = stg + (NMAT - (NMMA == 3 ? 2 : 1)) * MATB;
        const uint32_t Bbl = stg + 3 * MATB;                   // NMMA==3

        #pragma unroll
        for (int kk = 0; kk < 4; kk++) {
            uint32_t ah[4][4], al[4][4], bh[2][4], bl[2][4];
            #pragma unroll
            for (int mt = 0; mt < 4; mt++) {
                int row = warp_m * 64 + mt * 16 + (sel & 1) * 8 + r8;
                int cidx = kk * 2 + (sel >> 1);
                uint32_t off = (uint32_t)(row * 128) + ((uint32_t)(cidx ^ (row & 7)) * 16);
                ldsm4(ah[mt][0], ah[mt][1], ah[mt][2], ah[mt][3], Abh + off);
                if (NMMA >= 2)
                    ldsm4(al[mt][0], al[mt][1], al[mt][2], al[mt][3], Abl + off);
            }
            #pragma unroll
            for (int nb = 0; nb < 2; nb++) {
                int n = warp_n * 32 + nb * 16 + (sel >> 1) * 8 + r8;
                int cidx = kk * 2 + (sel & 1);
                uint32_t off = (uint32_t)(n * 128) + ((uint32_t)(cidx ^ (n & 7)) * 16);
                ldsm4(bh[nb][0], bh[nb][1], bh[nb][2], bh[nb][3], Bbh + off);
                if (NMMA == 3)
                    ldsm4(bl[nb][0], bl[nb][1], bl[nb][2], bl[nb][3], Bbl + off);
            }
            #pragma unroll
            for (int mt = 0; mt < 4; mt++)
                #pragma unroll
                for (int nt = 0; nt < 4; nt++) {
                    const uint32_t* bph = &bh[nt >> 1][(nt & 1) * 2];
                    mma16816h(acc[mt][nt], ah[mt], bph);
                    if (NMMA == 3) {
                        const uint32_t* bpl = &bl[nt >> 1][(nt & 1) * 2];
                        mma16816h(acc[mt][nt], ah[mt], bpl);
                    }
                    if (NMMA >= 2)
                        mma16816h(acc[mt][nt], al[mt], bph);
                }
        }
    }
    __syncthreads();

    // ---- epilogue: frags -> padded SMEM fp32 -> coalesced global ----------
    float* cs = (float*)smem;                   // 128 x 133 fp32 (68 KB)
    const int g = lane >> 2, tq = lane & 3;
    #pragma unroll
    for (int mt = 0; mt < 4; mt++) {
        int rb = warp_m * 64 + mt * 16 + g;
        #pragma unroll
        for (int nt = 0; nt < 4; nt++) {
            int cb = warp_n * 32 + nt * 8 + tq * 2;
            cs[rb * 133 + cb]           = acc[mt][nt][0];
            cs[rb * 133 + cb + 1]       = acc[mt][nt][1];
            cs[(rb + 8) * 133 + cb]     = acc[mt][nt][2];
            cs[(rb + 8) * 133 + cb + 1] = acc[mt][nt][3];
        }
    }
    __syncthreads();

    if (MODE == 0) {
        const int col = tid & 127, half = tid >> 7;
        const float bv = bias ? __ldg(bias + col0 + col) : 0.f;
        for (int r = half; r < 128; r += 2)
            Cf[(size_t)(row0 + r) * ldc + col0 + col] = cs[r * 133 + col] + bv;
    } else if (MODE == 1) {
        const int col = tid & 127, half = tid >> 7;
        const float bv = bias ? __ldg(bias + col0 + col) : 0.f;
        for (int r = half; r < 128; r += 2) {
            float v = cs[r * 133 + col] + bv;
            __half h = __float2half(v);
            size_t idx = (size_t)(row0 + r) * ldc + col0 + col;
            Ch[idx] = h;
            Cl[idx] = __float2half(v - __half2float(h));
        }
    } else if (MODE == 2) {                     // fp16 single, transposed
        const int row = tid & 127, half = tid >> 7;
        for (int c = half; c < 128; c += 2) {
            float v = cs[row * 133 + c] + (bias ? __ldg(bias + col0 + c) : 0.f);
            Ch[(size_t)(col0 + c) * ldc + row0 + row] = __float2half(v);
        }
    } else {                                    // MODE 3: fp16 single, *rinv
        const int col = tid & 127, half = tid >> 7;
        for (int r = half; r < 128; r += 2) {
            float v = cs[r * 133 + col] * __ldg(rinv + row0 + r);
            Ch[(size_t)(row0 + r) * ldc + col0 + col] = __float2half(v);
        }
    }
}

// ======================= fp32 -> fp16 conversions (float4) ==================
__global__ __launch_bounds__(256)
void convert_pair(const float* __restrict__ s, __half* __restrict__ h,
                  __half* __restrict__ l, size_t n4)
{
    size_t i = (size_t)blockIdx.x * blockDim.x + threadIdx.x;
    const size_t stride = (size_t)gridDim.x * blockDim.x;
    for (; i < n4; i += stride) {
        float4 v = ((const float4*)s)[i];
        __half h0 = __float2half(v.x), h1 = __float2half(v.y);
        __half h2 = __float2half(v.z), h3 = __float2half(v.w);
        __half2 hp0 = {h0, h1}, hp1 = {h2, h3};
        __half2 lp0 = {__float2half(v.x - __half2float(h0)),
                       __float2half(v.y - __half2float(h1))};
        __half2 lp1 = {__float2half(v.z - __half2float(h2)),
                       __float2half(v.w - __half2float(h3))};
        ((__half2*)h)[i * 2]     = hp0;
        ((__half2*)h)[i * 2 + 1] = hp1;
        ((__half2*)l)[i * 2]     = lp0;
        ((__half2*)l)[i * 2 + 1] = lp1;
    }
}

__global__ __launch_bounds__(256)
void convert_single(const float* __restrict__ s, __half* __restrict__ h, size_t n4)
{
    size_t i = (size_t)blockIdx.x * blockDim.x + threadIdx.x;
    const size_t stride = (size_t)gridDim.x * blockDim.x;
    for (; i < n4; i += stride) {
        float4 v = ((const float4*)s)[i];
        __half2 hp0 = {__float2half(v.x), __float2half(v.y)};
        __half2 hp1 = {__float2half(v.z), __float2half(v.w)};
        ((__half2*)h)[i * 2]     = hp0;
        ((__half2*)h)[i * 2 + 1] = hp1;
    }
}

__global__ void concat_bias(const float* a, const float* b, float* dst) {
    int t = threadIdx.x;                        // 256 threads
    dst[t] = (t < HDIM) ? a[t] : b[t - HDIM];
}

// ======= softmax: fp32 scores -> UNNORMALIZED fp16 single + fp32 1/rowsum ===
__global__ __launch_bounds__(256)
void softmax_h(const float* __restrict__ S, __half* __restrict__ Ph,
               float* __restrict__ rinv, int n, float scale)
{
    __shared__ float red[256];
    const int tid = threadIdx.x;
    const float* row = S + (size_t)blockIdx.x * n;
    __half* oh = Ph + (size_t)blockIdx.x * n;

    constexpr int PER2 = NTOK / 512;  // 16 float2 per thread
    float v[2 * PER2];
    float mx = -1e30f;
    #pragma unroll
    for (int i = 0; i < PER2; i++) {
        float2 f = ((const float2*)row)[i * 256 + tid];
        v[2 * i] = f.x; v[2 * i + 1] = f.y;
        mx = fmaxf(mx, fmaxf(f.x, f.y));
    }
    red[tid] = mx; __syncthreads();
    #pragma unroll
    for (int s = 128; s > 0; s >>= 1) {
        if (tid < s) red[tid] = fmaxf(red[tid], red[tid + s]);
        __syncthreads();
    }
    mx = red[0]; __syncthreads();

    const float k2 = scale * 1.4426950408889634f;
    float sum = 0.f;
    #pragma unroll
    for (int i = 0; i < 2 * PER2; i++) {
        v[i] = fast_exp2((v[i] - mx) * k2);
        sum += v[i];
    }
    red[tid] = sum; __syncthreads();
    #pragma unroll
    for (int s = 128; s > 0; s >>= 1) {
        if (tid < s) red[tid] += red[tid + s];
        __syncthreads();
    }
    if (tid == 0) rinv[blockIdx.x] = 1.0f / red[0];

    #pragma unroll
    for (int i = 0; i < PER2; i++) {
        __half2 h = {__float2half(v[2 * i]), __float2half(v[2 * i + 1])};
        ((__half2*)oh)[i * 256 + tid] = h;
    }
}

// ======================= launch =============================================
extern "C" void kernel_launch(void* const* d_in, const int* /*in_sizes*/, int /*n_in*/,
                              void* d_out, int /*out_size*/)
{
    const float* x  = (const float*)d_in[0];
    const float* Wq = (const float*)d_in[1];
    const float* bq = (const float*)d_in[2];
    const float* Wk = (const float*)d_in[3];
    const float* bk = (const float*)d_in[4];
    const float* Wv = (const float*)d_in[5];
    const float* bv = (const float*)d_in[6];
    const float* Wo = (const float*)d_in[7];
    const float* bo = (const float*)d_in[8];
    float* out = (float*)d_out;

    __half *xh, *xl, *wqkh, *wqkl, *wvh, *woh;
    __half *qkh, *qkl, *vth, *ph, *oh;
    float *sc, *rinv, *bqk;
    cudaGetSymbolAddress((void**)&xh,   g_xh);   cudaGetSymbolAddress((void**)&xl,   g_xl);
    cudaGetSymbolAddress((void**)&wqkh, g_wqkh); cudaGetSymbolAddress((void**)&wqkl, g_wqkl);
    cudaGetSymbolAddress((void**)&wvh,  g_wvh);  cudaGetSymbolAddress((void**)&woh,  g_woh);
    cudaGetSymbolAddress((void**)&qkh,  g_qkh);  cudaGetSymbolAddress((void**)&qkl,  g_qkl);
    cudaGetSymbolAddress((void**)&vth,  g_vth);  cudaGetSymbolAddress((void**)&ph,   g_ph);
    cudaGetSymbolAddress((void**)&oh,   g_oh);
    cudaGetSymbolAddress((void**)&sc,   g_sc);   cudaGetSymbolAddress((void**)&rinv, g_rinv);
    cudaGetSymbolAddress((void**)&bqk,  g_bqk);

    cudaFuncSetAttribute(gemm_h<3,1>, cudaFuncAttributeMaxDynamicSharedMemorySize, SMEM_MAX);
    cudaFuncSetAttribute(gemm_h<2,2>, cudaFuncAttributeMaxDynamicSharedMemorySize, SMEM_MAX);
    cudaFuncSetAttribute(gemm_h<3,0>, cudaFuncAttributeMaxDynamicSharedMemorySize, SMEM_MAX);
    cudaFuncSetAttribute(gemm_h<1,3>, cudaFuncAttributeMaxDynamicSharedMemorySize, SMEM_MAX);
    cudaFuncSetAttribute(gemm_h<1,0>, cudaFuncAttributeMaxDynamicSharedMemorySize, SMEM_MAX);

    const float scale = 0.08838834764831845f;  // 1/sqrt(128)
    const dim3 blk(256);

    // input conversions
    convert_pair<<<592, 256>>>(x,  xh,  xl,  (size_t)NTOK * CDIM / 4);
    convert_pair<<<32,  256>>>(Wq, wqkh, wqkl, (size_t)HDIM * CDIM / 4);
    convert_pair<<<32,  256>>>(Wk, wqkh + (size_t)HDIM * CDIM,
                               wqkl + (size_t)HDIM * CDIM, (size_t)HDIM * CDIM / 4);
    convert_single<<<256, 256>>>(Wv, wvh, (size_t)CDIM * CDIM / 4);
    convert_single<<<256, 256>>>(Wo, woh, (size_t)CDIM * CDIM / 4);
    concat_bias<<<1, 256>>>(bq, bk, bqk);

    // qk = x @ [Wq;Wk]^T + bqk -> fp16 pair, 8192 x 256   (3-term)
    gemm_h<3,1><<<dim3(2, 64), blk, SMEM_MAX>>>(xh, xl, wqkh, wqkl, bqk, nullptr,
        nullptr, qkh, qkl, NTOK, 2 * HDIM, CDIM, CDIM, CDIM, 2 * HDIM);
    // v^T = (x @ Wv^T + bv)^T -> fp16 single, stored [C, N]   (2-term)
    gemm_h<2,2><<<dim3(8, 64), blk, SMEM_MAX>>>(xh, xl, wvh, nullptr, bv, nullptr,
        nullptr, vth, nullptr, NTOK, CDIM, CDIM, CDIM, CDIM, NTOK);
    // scores = q @ k^T -> fp32   (3-term; q/k are slices of qk, ld=256)
    gemm_h<3,0><<<dim3(64, 64), blk, SMEM_MAX>>>(qkh, qkl, qkh + HDIM, qkl + HDIM,
        nullptr, nullptr, sc, nullptr, nullptr, NTOK, NTOK, HDIM, 2 * HDIM, 2 * HDIM, NTOK);
    // softmax rows -> unnormalized fp16 single + 1/rowsum
    softmax_h<<<NTOK, 256>>>(sc, ph, rinv, NTOK, scale);
    // att = (P @ v) * rinv -> fp16 single   (dominant GEMM, 1 MMA/tile)
    gemm_h<1,3><<<dim3(8, 64), blk, SMEM_MAX>>>(ph, nullptr, vth, nullptr,
        nullptr, rinv, nullptr, oh, nullptr, NTOK, CDIM, NTOK, NTOK, NTOK, CDIM);
    // out = att @ Wo^T + bo -> fp32   (1-term: att single x Wo single)
    gemm_h<1,0><<<dim3(8, 64), blk, SMEM_MAX>>>(oh, nullptr, woh, nullptr, bo, nullptr,
        out, nullptr, nullptr, NTOK, CDIM, CDIM, CDIM, CDIM, CDIM);
}

// round 17
// speedup vs baseline: 6.3792x; 1.0922x over previous
#include <cuda_runtime.h>
#include <cuda_fp16.h>
#include <cstdint>
#include <cstddef>

#define NTOK 8192
#define CDIM 1024
#define HDIM 128

// ======================= scratch (static, allocation-free) ==================
__device__ __align__(16) __half g_xh  [(size_t)NTOK * CDIM];
__device__ __align__(16) __half g_xl  [(size_t)NTOK * CDIM];
__device__ __align__(16) __half g_wqkh[2 * HDIM * CDIM];     // [Wq;Wk] pair
__device__ __align__(16) __half g_wqkl[2 * HDIM * CDIM];
__device__ float g_bqk[2 * HDIM];
__device__ __align__(16) __half g_wvh [CDIM * CDIM];         // Wv fp16 single
__device__ __align__(16) __half g_woh [CDIM * CDIM];         // Wo fp16 single
__device__ __align__(16) __half g_qkh [(size_t)NTOK * 2 * HDIM]; // q|k pair
__device__ __align__(16) __half g_qkl [(size_t)NTOK * 2 * HDIM];
__device__ __align__(16) __half g_vth [(size_t)CDIM * NTOK];     // v^T fp16 single
__device__ float g_sc[(size_t)NTOK * NTOK];                      // scores fp32
__device__ __align__(16) __half g_ph  [(size_t)NTOK * NTOK];     // exp fp16 single
__device__ float g_rinv[NTOK];                                   // 1/rowsum
__device__ __align__(16) __half g_oh  [(size_t)NTOK * CDIM];     // attn@v fp16 single

// ======================= PTX helpers (sm_80+ portable only) =================
__device__ __forceinline__ uint32_t smem_u32(const void* p) {
    uint32_t a;
    asm("{ .reg .u64 t; cvta.to.shared.u64 t, %1; cvt.u32.u64 %0, t; }" : "=r"(a) : "l"(p));
    return a;
}
#define CP16(sm, gp) \
    asm volatile("cp.async.cg.shared.global [%0], [%1], 16;" :: "r"(sm), "l"(gp))
#define CP_COMMIT() asm volatile("cp.async.commit_group;" ::: "memory")

__device__ __forceinline__ void ldsm4(uint32_t& r0, uint32_t& r1, uint32_t& r2,
                                      uint32_t& r3, uint32_t a) {
    asm volatile("ldmatrix.sync.aligned.m8n8.x4.shared.b16 {%0,%1,%2,%3}, [%4];"
                 : "=r"(r0), "=r"(r1), "=r"(r2), "=r"(r3) : "r"(a));
}
__device__ __forceinline__ void mma16816h(float* c, const uint32_t* a, const uint32_t* b) {
    asm volatile("mma.sync.aligned.m16n8k16.row.col.f32.f16.f16.f32 "
                 "{%0,%1,%2,%3}, {%4,%5,%6,%7}, {%8,%9}, {%0,%1,%2,%3};"
                 : "+f"(c[0]), "+f"(c[1]), "+f"(c[2]), "+f"(c[3])
                 : "r"(a[0]), "r"(a[1]), "r"(a[2]), "r"(a[3]), "r"(b[0]), "r"(b[1]));
}

// FMA-pipe exp2: ~2.4e-6 max rel err, no MUFU.
__device__ __forceinline__ float fast_exp2(float y) {
    y = fmaxf(y, -120.f);
    const int   ni = __float2int_rn(y);
    const float f  = y - (float)ni;
    float p = 1.3333558146e-3f;
    p = fmaf(p, f, 9.6181291076e-3f);
    p = fmaf(p, f, 5.5504108664e-2f);
    p = fmaf(p, f, 2.4022650696e-1f);
    p = fmaf(p, f, 6.9314718056e-1f);
    p = fmaf(p, f, 1.0f);
    return p * __int_as_float((ni + 127) << 23);
}

#define SWZ(off) ((off) ^ (((off) >> 3) & 0x70))
static constexpr int BK   = 64;
static constexpr int MATB = 128 * 128;              // 16 KB tile (128 rows x 128B)

// ======================= unified fp16 GEMM ==================================
// C = A @ B^T (+bias[col]) (*rinv[row]).  A: M x K, B: N x K.
// NMMA 3: A pair x B pair (hh + hl + lh)   NMMA 2: A pair x B single
// NMMA 1: A single x B single
// MODE 0: fp32 row-major + bias           MODE 1: fp16 pair row-major + bias
// MODE 2: fp16 single transposed + bias   MODE 3: fp16 single row-major * rinv
// BM=BN=128, BK=64, 256 threads (8 warps, 64x32 warp tiles).
// Occupancy plan: NMMA=3 -> 4 mats x 3 stages = 192 KB, 1 CTA/SM.
//                 NMMA=2 -> 3 mats x 2 stages =  96 KB, 2 CTAs/SM.
//                 NMMA=1 -> 2 mats x 3 stages =  96 KB, 2 CTAs/SM.
template<int N_> struct GCfg {
    static constexpr int NMAT = (N_ == 3) ? 4 : (N_ == 2) ? 3 : 2;
    static constexpr int STG  = (N_ == 3) ? 3 : (N_ == 2) ? 2 : 3;
    static constexpr int OCC  = (N_ == 3) ? 1 : 2;
    static constexpr int SMEM = STG * NMAT * MATB;
};

template<int NMMA, int MODE>
__global__ __launch_bounds__(256, GCfg<NMMA>::OCC)
void gemm_h(const __half* __restrict__ Ah, const __half* __restrict__ Al,
            const __half* __restrict__ Bh, const __half* __restrict__ Bl,
            const float* __restrict__ bias, const float* __restrict__ rinv,
            float* __restrict__ Cf, __half* __restrict__ Ch, __half* __restrict__ Cl,
            int M, int N, int K, int lda, int ldb, int ldc)
{
    constexpr int NMAT = GCfg<NMMA>::NMAT;
    constexpr int STG  = GCfg<NMMA>::STG;
    constexpr int STB  = NMAT * MATB;

    extern __shared__ __align__(128) char smem[];
    const uint32_t sb = smem_u32(smem);

    const int tid  = threadIdx.x;
    const int lane = tid & 31;
    const int wid  = tid >> 5;
    const int warp_m = wid & 1;
    const int warp_n = wid >> 1;
    const int row0 = blockIdx.y * 128;
    const int col0 = blockIdx.x * 128;

    // ---- loader groups: 4 x 64 threads ------------------------------------
    const int grp = tid >> 6, lt = tid & 63;
    const __half* gbase; uint32_t smoff; int c0, nch, gld;
    if (NMMA == 3) {
        const __half* gs[4] = {Ah + (size_t)row0 * lda, Al + (size_t)row0 * lda,
                               Bh + (size_t)col0 * ldb, Bl + (size_t)col0 * ldb};
        gbase = gs[grp]; smoff = (uint32_t)grp * MATB; c0 = 0; nch = 16;
        gld = (grp < 2) ? lda : ldb;
    } else if (NMMA == 2) {
        if (grp == 0)      { gbase = Ah + (size_t)row0 * lda; smoff = 0;        c0 = 0;   nch = 16; gld = lda; }
        else if (grp == 1) { gbase = Al + (size_t)row0 * lda; smoff = MATB;     c0 = 0;   nch = 16; gld = lda; }
        else if (grp == 2) { gbase = Bh + (size_t)col0 * ldb; smoff = 2 * MATB; c0 = 0;   nch = 8;  gld = ldb; }
        else               { gbase = Bh + (size_t)col0 * ldb; smoff = 2 * MATB; c0 = 512; nch = 8;  gld = ldb; }
    } else {
        if (grp == 0)      { gbase = Ah + (size_t)row0 * lda; smoff = 0;    c0 = 0;   nch = 8; gld = lda; }
        else if (grp == 1) { gbase = Ah + (size_t)row0 * lda; smoff = 0;    c0 = 512; nch = 8; gld = lda; }
        else if (grp == 2) { gbase = Bh + (size_t)col0 * ldb; smoff = MATB; c0 = 0;   nch = 8; gld = ldb; }
        else               { gbase = Bh + (size_t)col0 * ldb; smoff = MATB; c0 = 512; nch = 8; gld = ldb; }
    }

    auto load_stage = [&](int s, int buf) {
        const __half* gp = gbase + (size_t)s * BK;
        const uint32_t sbuf = sb + smoff + (uint32_t)buf * STB;
        #pragma unroll
        for (int i = 0; i < 16; i++) {
            if (i >= nch) break;
            int c = c0 + i * 64 + lt;
            int r = c >> 3, g = c & 7;
            uint32_t off = (uint32_t)(r * 128 + g * 16);
            CP16(sbuf + SWZ(off), gp + (size_t)r * gld + g * 8);
        }
    };

    float acc[4][4][4];
    #pragma unroll
    for (int i = 0; i < 4; i++)
        #pragma unroll
        for (int j = 0; j < 4; j++)
            #pragma unroll
            for (int e = 0; e < 4; e++) acc[i][j][e] = 0.f;

    const int S = K / BK;
    #pragma unroll
    for (int i = 0; i < STG - 1; i++) {
        if (i < S) load_stage(i, i);
        CP_COMMIT();
    }

    const int sel = lane >> 3, r8 = lane & 7;

    for (int s = 0; s < S; s++) {
        asm volatile("cp.async.wait_group %0;" :: "n"(STG - 2) : "memory");
        __syncthreads();
        if (s + STG - 1 < S) load_stage(s + STG - 1, (s + STG - 1) % STG);
        CP_COMMIT();

        const uint32_t stg = sb + (uint32_t)(s % STG) * STB;
        const uint32_t Abh = stg;
        const uint32_t Abl = stg + MATB;                       // NMMA>=2
        const uint32_t Bbh = stg + (NMAT - (NMMA == 3 ? 2 : 1)) * MATB;
        const uint32_t Bbl = stg + 3 * MATB;                   // NMMA==3

        #pragma unroll
        for (int kk = 0; kk < 4; kk++) {
            uint32_t ah[4][4], al[4][4], bh[2][4], bl[2][4];
            #pragma unroll
            for (int mt = 0; mt < 4; mt++) {
                int row = warp_m * 64 + mt * 16 + (sel & 1) * 8 + r8;
                int cidx = kk * 2 + (sel >> 1);
                uint32_t off = (uint32_t)(row * 128) + ((uint32_t)(cidx ^ (row & 7)) * 16);
                ldsm4(ah[mt][0], ah[mt][1], ah[mt][2], ah[mt][3], Abh + off);
                if (NMMA >= 2)
                    ldsm4(al[mt][0], al[mt][1], al[mt][2], al[mt][3], Abl + off);
            }
            #pragma unroll
            for (int nb = 0; nb < 2; nb++) {
                int n = warp_n * 32 + nb * 16 + (sel >> 1) * 8 + r8;
                int cidx = kk * 2 + (sel & 1);
                uint32_t off = (uint32_t)(n * 128) + ((uint32_t)(cidx ^ (n & 7)) * 16);
                ldsm4(bh[nb][0], bh[nb][1], bh[nb][2], bh[nb][3], Bbh + off);
                if (NMMA == 3)
                    ldsm4(bl[nb][0], bl[nb][1], bl[nb][2], bl[nb][3], Bbl + off);
            }
            #pragma unroll
            for (int mt = 0; mt < 4; mt++)
                #pragma unroll
                for (int nt = 0; nt < 4; nt++) {
                    const uint32_t* bph = &bh[nt >> 1][(nt & 1) * 2];
                    mma16816h(acc[mt][nt], ah[mt], bph);
                    if (NMMA == 3) {
                        const uint32_t* bpl = &bl[nt >> 1][(nt & 1) * 2];
                        mma16816h(acc[mt][nt], ah[mt], bpl);
                    }
                    if (NMMA >= 2)
                        mma16816h(acc[mt][nt], al[mt], bph);
                }
        }
    }
    __syncthreads();

    // ---- epilogue: frags -> padded SMEM fp32 -> coalesced global ----------
    float* cs = (float*)smem;                   // 128 x 133 fp32 (68 KB <= 96 KB)
    const int g = lane >> 2, tq = lane & 3;
    #pragma unroll
    for (int mt = 0; mt < 4; mt++) {
        int rb = warp_m * 64 + mt * 16 + g;
        #pragma unroll
        for (int nt = 0; nt < 4; nt++) {
            int cb = warp_n * 32 + nt * 8 + tq * 2;
            cs[rb * 133 + cb]           = acc[mt][nt][0];
            cs[rb * 133 + cb + 1]       = acc[mt][nt][1];
            cs[(rb + 8) * 133 + cb]     = acc[mt][nt][2];
            cs[(rb + 8) * 133 + cb + 1] = acc[mt][nt][3];
        }
    }
    __syncthreads();

    if (MODE == 0) {
        const int col = tid & 127, half = tid >> 7;
        const float bv = bias ? __ldg(bias + col0 + col) : 0.f;
        for (int r = half; r < 128; r += 2)
            Cf[(size_t)(row0 + r) * ldc + col0 + col] = cs[r * 133 + col] + bv;
    } else if (MODE == 1) {
        const int col = tid & 127, half = tid >> 7;
        const float bv = bias ? __ldg(bias + col0 + col) : 0.f;
        for (int r = half; r < 128; r += 2) {
            float v = cs[r * 133 + col] + bv;
            __half h = __float2half(v);
            size_t idx = (size_t)(row0 + r) * ldc + col0 + col;
            Ch[idx] = h;
            Cl[idx] = __float2half(v - __half2float(h));
        }
    } else if (MODE == 2) {                     // fp16 single, transposed
        const int row = tid & 127, half = tid >> 7;
        for (int c = half; c < 128; c += 2) {
            float v = cs[row * 133 + c] + (bias ? __ldg(bias + col0 + c) : 0.f);
            Ch[(size_t)(col0 + c) * ldc + row0 + row] = __float2half(v);
        }
    } else {                                    // MODE 3: fp16 single, *rinv
        const int col = tid & 127, half = tid >> 7;
        for (int r = half; r < 128; r += 2) {
            float v = cs[r * 133 + col] * __ldg(rinv + row0 + r);
            Ch[(size_t)(row0 + r) * ldc + col0 + col] = __float2half(v);
        }
    }
}

// ======================= fp32 -> fp16 conversions (float4) ==================
__global__ __launch_bounds__(256)
void convert_pair(const float* __restrict__ s, __half* __restrict__ h,
                  __half* __restrict__ l, size_t n4)
{
    size_t i = (size_t)blockIdx.x * blockDim.x + threadIdx.x;
    const size_t stride = (size_t)gridDim.x * blockDim.x;
    for (; i < n4; i += stride) {
        float4 v = ((const float4*)s)[i];
        __half h0 = __float2half(v.x), h1 = __float2half(v.y);
        __half h2 = __float2half(v.z), h3 = __float2half(v.w);
        __half2 hp0 = {h0, h1}, hp1 = {h2, h3};
        __half2 lp0 = {__float2half(v.x - __half2float(h0)),
                       __float2half(v.y - __half2float(h1))};
        __half2 lp1 = {__float2half(v.z - __half2float(h2)),
                       __float2half(v.w - __half2float(h3))};
        ((__half2*)h)[i * 2]     = hp0;
        ((__half2*)h)[i * 2 + 1] = hp1;
        ((__half2*)l)[i * 2]     = lp0;
        ((__half2*)l)[i * 2 + 1] = lp1;
    }
}

__global__ __launch_bounds__(256)
void convert_single(const float* __restrict__ s, __half* __restrict__ h, size_t n4)
{
    size_t i = (size_t)blockIdx.x * blockDim.x + threadIdx.x;
    const size_t stride = (size_t)gridDim.x * blockDim.x;
    for (; i < n4; i += stride) {
        float4 v = ((const float4*)s)[i];
        __half2 hp0 = {__float2half(v.x), __float2half(v.y)};
        __half2 hp1 = {__float2half(v.z), __float2half(v.w)};
        ((__half2*)h)[i * 2]     = hp0;
        ((__half2*)h)[i * 2 + 1] = hp1;
    }
}

__global__ void concat_bias(const float* a, const float* b, float* dst) {
    int t = threadIdx.x;                        // 256 threads
    dst[t] = (t < HDIM) ? a[t] : b[t - HDIM];
}

// ======= softmax: fp32 scores -> UNNORMALIZED fp16 single + fp32 1/rowsum ===
__global__ __launch_bounds__(256)
void softmax_h(const float* __restrict__ S, __half* __restrict__ Ph,
               float* __restrict__ rinv, int n, float scale)
{
    __shared__ float red[256];
    const int tid = threadIdx.x;
    const float* row = S + (size_t)blockIdx.x * n;
    __half* oh = Ph + (size_t)blockIdx.x * n;

    constexpr int PER2 = NTOK / 512;  // 16 float2 per thread
    float v[2 * PER2];
    float mx = -1e30f;
    #pragma unroll
    for (int i = 0; i < PER2; i++) {
        float2 f = ((const float2*)row)[i * 256 + tid];
        v[2 * i] = f.x; v[2 * i + 1] = f.y;
        mx = fmaxf(mx, fmaxf(f.x, f.y));
    }
    red[tid] = mx; __syncthreads();
    #pragma unroll
    for (int s = 128; s > 0; s >>= 1) {
        if (tid < s) red[tid] = fmaxf(red[tid], red[tid + s]);
        __syncthreads();
    }
    mx = red[0]; __syncthreads();

    const float k2 = scale * 1.4426950408889634f;
    float sum = 0.f;
    #pragma unroll
    for (int i = 0; i < 2 * PER2; i++) {
        v[i] = fast_exp2((v[i] - mx) * k2);
        sum += v[i];
    }
    red[tid] = sum; __syncthreads();
    #pragma unroll
    for (int s = 128; s > 0; s >>= 1) {
        if (tid < s) red[tid] += red[tid + s];
        __syncthreads();
    }
    if (tid == 0) rinv[blockIdx.x] = 1.0f / red[0];

    #pragma unroll
    for (int i = 0; i < PER2; i++) {
        __half2 h = {__float2half(v[2 * i]), __float2half(v[2 * i + 1])};
        ((__half2*)oh)[i * 256 + tid] = h;
    }
}

// ======================= launch =============================================
extern "C" void kernel_launch(void* const* d_in, const int* /*in_sizes*/, int /*n_in*/,
                              void* d_out, int /*out_size*/)
{
    const float* x  = (const float*)d_in[0];
    const float* Wq = (const float*)d_in[1];
    const float* bq = (const float*)d_in[2];
    const float* Wk = (const float*)d_in[3];
    const float* bk = (const float*)d_in[4];
    const float* Wv = (const float*)d_in[5];
    const float* bv = (const float*)d_in[6];
    const float* Wo = (const float*)d_in[7];
    const float* bo = (const float*)d_in[8];
    float* out = (float*)d_out;

    __half *xh, *xl, *wqkh, *wqkl, *wvh, *woh;
    __half *qkh, *qkl, *vth, *ph, *oh;
    float *sc, *rinv, *bqk;
    cudaGetSymbolAddress((void**)&xh,   g_xh);   cudaGetSymbolAddress((void**)&xl,   g_xl);
    cudaGetSymbolAddress((void**)&wqkh, g_wqkh); cudaGetSymbolAddress((void**)&wqkl, g_wqkl);
    cudaGetSymbolAddress((void**)&wvh,  g_wvh);  cudaGetSymbolAddress((void**)&woh,  g_woh);
    cudaGetSymbolAddress((void**)&qkh,  g_qkh);  cudaGetSymbolAddress((void**)&qkl,  g_qkl);
    cudaGetSymbolAddress((void**)&vth,  g_vth);  cudaGetSymbolAddress((void**)&ph,   g_ph);
    cudaGetSymbolAddress((void**)&oh,   g_oh);
    cudaGetSymbolAddress((void**)&sc,   g_sc);   cudaGetSymbolAddress((void**)&rinv, g_rinv);
    cudaGetSymbolAddress((void**)&bqk,  g_bqk);

    constexpr int SM3 = GCfg<3>::SMEM;   // 192 KB
    constexpr int SM2 = GCfg<2>::SMEM;   //  96 KB
    constexpr int SM1 = GCfg<1>::SMEM;   //  96 KB
    cudaFuncSetAttribute(gemm_h<3,1>, cudaFuncAttributeMaxDynamicSharedMemorySize, SM3);
    cudaFuncSetAttribute(gemm_h<3,0>, cudaFuncAttributeMaxDynamicSharedMemorySize, SM3);
    cudaFuncSetAttribute(gemm_h<2,2>, cudaFuncAttributeMaxDynamicSharedMemorySize, SM2);
    cudaFuncSetAttribute(gemm_h<1,3>, cudaFuncAttributeMaxDynamicSharedMemorySize, SM1);
    cudaFuncSetAttribute(gemm_h<1,0>, cudaFuncAttributeMaxDynamicSharedMemorySize, SM1);

    const float scale = 0.08838834764831845f;  // 1/sqrt(128)
    const dim3 blk(256);

    // input conversions
    convert_pair<<<592, 256>>>(x,  xh,  xl,  (size_t)NTOK * CDIM / 4);
    convert_pair<<<32,  256>>>(Wq, wqkh, wqkl, (size_t)HDIM * CDIM / 4);
    convert_pair<<<32,  256>>>(Wk, wqkh + (size_t)HDIM * CDIM,
                               wqkl + (size_t)HDIM * CDIM, (size_t)HDIM * CDIM / 4);
    convert_single<<<256, 256>>>(Wv, wvh, (size_t)CDIM * CDIM / 4);
    convert_single<<<256, 256>>>(Wo, woh, (size_t)CDIM * CDIM / 4);
    concat_bias<<<1, 256>>>(bq, bk, bqk);

    // qk = x @ [Wq;Wk]^T + bqk -> fp16 pair, 8192 x 256   (3-term)
    gemm_h<3,1><<<dim3(2, 64), blk, SM3>>>(xh, xl, wqkh, wqkl, bqk, nullptr,
        nullptr, qkh, qkl, NTOK, 2 * HDIM, CDIM, CDIM, CDIM, 2 * HDIM);
    // v^T = (x @ Wv^T + bv)^T -> fp16 single, stored [C, N]   (2-term)
    gemm_h<2,2><<<dim3(8, 64), blk, SM2>>>(xh, xl, wvh, nullptr, bv, nullptr,
        nullptr, vth, nullptr, NTOK, CDIM, CDIM, CDIM, CDIM, NTOK);
    // scores = q @ k^T -> fp32   (3-term; q/k are slices of qk, ld=256)
    gemm_h<3,0><<<dim3(64, 64), blk, SM3>>>(qkh, qkl, qkh + HDIM, qkl + HDIM,
        nullptr, nullptr, sc, nullptr, nullptr, NTOK, NTOK, HDIM, 2 * HDIM, 2 * HDIM, NTOK);
    // softmax rows -> unnormalized fp16 single + 1/rowsum
    softmax_h<<<NTOK, 256>>>(sc, ph, rinv, NTOK, scale);
    // att = (P @ v) * rinv -> fp16 single   (dominant GEMM, 1 MMA/tile)
    gemm_h<1,3><<<dim3(8, 64), blk, SM1>>>(ph, nullptr, vth, nullptr,
        nullptr, rinv, nullptr, oh, nullptr, NTOK, CDIM, NTOK, NTOK, NTOK, CDIM);
    // out = att @ Wo^T + bo -> fp32   (1-term: att single x Wo single)
    gemm_h<1,0><<<dim3(8, 64), blk, SM1>>>(oh, nullptr, woh, nullptr, bo, nullptr,
        out, nullptr, nullptr, NTOK, CDIM, CDIM, CDIM, CDIM, CDIM);
}